// round 9
// baseline (speedup 1.0000x reference)
#include <cuda_runtime.h>
#include <math.h>

#define NN 100000
#define NE 1600000
#define NBLK_SCAN 98   // ceil(NN/1024)

// ---------------- tf32 helpers ----------------
__device__ __forceinline__ unsigned tf32_of(float x) {
    unsigned r; asm("cvt.rna.tf32.f32 %0, %1;" : "=r"(r) : "f"(x)); return r;
}
__device__ __forceinline__ void mma_tf32(float* c,
                                         unsigned a0, unsigned a1, unsigned a2, unsigned a3,
                                         unsigned b0, unsigned b1) {
    asm("mma.sync.aligned.m16n8k8.row.col.f32.tf32.tf32.f32 "
        "{%0,%1,%2,%3}, {%4,%5,%6,%7}, {%8,%9}, {%0,%1,%2,%3};"
        : "+f"(c[0]), "+f"(c[1]), "+f"(c[2]), "+f"(c[3])
        : "r"(a0), "r"(a1), "r"(a2), "r"(a3), "r"(b0), "r"(b1));
}

// ---------------- device scratch (no allocations allowed) ----------------
__device__ int   g_is64;
__device__ int   g_src32[NE];
__device__ int   g_dst32[NE];
__device__ int   g_deg_out[NN];
__device__ int   g_deg_in[NN];
__device__ float g_rs_out[NN];
__device__ float g_rs_in[NN];
__device__ int   g_ptr[NN];
__device__ int   g_fill[NN];
__device__ int   g_bsum[128];
__device__ int   g_csr_src[NE];
__device__ float g_h1tmp[(size_t)NN * 128];
__device__ float g_agg1 [(size_t)NN * 128];
__device__ float g_h2tmp[(size_t)NN * 64];
__device__ float g_agg2 [(size_t)NN * 64];
__device__ float g_pre  [(size_t)NN * 128];   // [:,0:64]=a_pre(src), [:,64:128]=c_pre(dst)

// ---------------- zero degree counters + index-width detect ----------------
__global__ void zero_k(const void* src) {
    int tid = blockIdx.x * blockDim.x + threadIdx.x;
    int stride = gridDim.x * blockDim.x;
    for (int i = tid; i < NN; i += stride) { g_deg_out[i] = 0; g_deg_in[i] = 0; }
    if (blockIdx.x == 0 && threadIdx.x < 32) {
        const long long* p = (const long long*)src;
        bool ok = true;
        for (int i = threadIdx.x; i < 256; i += 32) {
            long long v = p[i];
            if (v < 0 || v >= NN) ok = false;
        }
        unsigned m = __ballot_sync(0xffffffffu, ok);
        if (threadIdx.x == 0) g_is64 = (m == 0xffffffffu) ? 1 : 0;
    }
}

// ---------------- normalize indices to int32 + degree histogram ----------------
__global__ void convert_deg_k(const void* srcp, const void* dstp) {
    int e = blockIdx.x * blockDim.x + threadIdx.x;
    if (e >= NE) return;
    int s, d;
    if (g_is64) {
        s = (int)((const long long*)srcp)[e];
        d = (int)((const long long*)dstp)[e];
    } else {
        s = ((const int*)srcp)[e];
        d = ((const int*)dstp)[e];
    }
    g_src32[e] = s;
    g_dst32[e] = d;
    atomicAdd(&g_deg_out[s], 1);
    atomicAdd(&g_deg_in[d], 1);
}

// ---------------- exclusive scan of deg_in ----------------
__global__ __launch_bounds__(1024) void scanA_k() {
    int n = blockIdx.x * 1024 + threadIdx.x;
    int v = (n < NN) ? g_deg_in[n] : 0;
    int lane = threadIdx.x & 31, wid = threadIdx.x >> 5;
    int x = v;
#pragma unroll
    for (int o = 1; o < 32; o <<= 1) {
        int y = __shfl_up_sync(0xffffffffu, x, o);
        if (lane >= o) x += y;
    }
    __shared__ int wsum[32];
    if (lane == 31) wsum[wid] = x;
    __syncthreads();
    if (wid == 0) {
        int t = wsum[lane];
#pragma unroll
        for (int o = 1; o < 32; o <<= 1) {
            int y = __shfl_up_sync(0xffffffffu, t, o);
            if (lane >= o) t += y;
        }
        wsum[lane] = t;
    }
    __syncthreads();
    int base = (wid > 0) ? wsum[wid - 1] : 0;
    int excl = base + x - v;
    if (n < NN) g_ptr[n] = excl;
    if (threadIdx.x == 1023) g_bsum[blockIdx.x] = excl + v;
}

__global__ void scanB_k() {
    int i = threadIdx.x, lane = i & 31, w = i >> 5;
    int v = (i < NBLK_SCAN) ? g_bsum[i] : 0;
    int x = v;
#pragma unroll
    for (int o = 1; o < 32; o <<= 1) {
        int y = __shfl_up_sync(0xffffffffu, x, o);
        if (lane >= o) x += y;
    }
    __shared__ int ws[4];
    if (lane == 31) ws[w] = x;
    __syncthreads();
    int off = 0;
    for (int k = 0; k < w; k++) off += ws[k];
    if (i < NBLK_SCAN) g_bsum[i] = off + x - v;
}

__global__ void scanC_k() {
    int n = blockIdx.x * 256 + threadIdx.x;
    if (n >= NN) return;
    int p = g_ptr[n] + g_bsum[n >> 10];
    g_ptr[n] = p;
    g_fill[n] = p;
    g_rs_out[n] = rsqrtf(fmaxf((float)g_deg_out[n], 1.f));
    g_rs_in[n]  = rsqrtf(fmaxf((float)g_deg_in[n],  1.f));
}

// ---------------- bin edges by dst ----------------
__global__ void bin_k() {
    int e = blockIdx.x * 256 + threadIdx.x;
    if (e >= NE) return;
    int d = g_dst32[e];
    int slot = atomicAdd(&g_fill[d], 1);
    g_csr_src[slot] = g_src32[e];
}

// ---------------- CSR aggregation: one warp per dst node ----------------
template<int DIM>
__global__ __launch_bounds__(256) void agg_k(const float* __restrict__ H,
                                             float* __restrict__ AG) {
    int warp = (blockIdx.x * 256 + threadIdx.x) >> 5;
    if (warp >= NN) return;
    int lane = threadIdx.x & 31;
    int ptr = g_ptr[warp];
    int deg = g_deg_in[warp];
    if (DIM == 128) {
        float4 acc = make_float4(0.f, 0.f, 0.f, 0.f);
        for (int base = 0; base < deg; base += 32) {
            int cnt = min(32, deg - base);
            int idx = (base + lane < deg) ? g_csr_src[ptr + base + lane] : 0;
            for (int j = 0; j < cnt; j++) {
                int s = __shfl_sync(0xffffffffu, idx, j);
                float4 v = *(const float4*)&H[(size_t)s * 128 + lane * 4];
                acc.x += v.x; acc.y += v.y; acc.z += v.z; acc.w += v.w;
            }
        }
        *(float4*)&AG[(size_t)warp * 128 + lane * 4] = acc;
    } else {
        float2 acc = make_float2(0.f, 0.f);
        for (int base = 0; base < deg; base += 32) {
            int cnt = min(32, deg - base);
            int idx = (base + lane < deg) ? g_csr_src[ptr + base + lane] : 0;
            for (int j = 0; j < cnt; j++) {
                int s = __shfl_sync(0xffffffffu, idx, j);
                float2 v = *(const float2*)&H[(size_t)s * 64 + lane * 2];
                acc.x += v.x; acc.y += v.y;
            }
        }
        *(float2*)&AG[(size_t)warp * 64 + lane * 2] = acc;
    }
}

// ---------------- node GEMM, k-major activation tile, scalar FFMA (R5-proven) ----------------
// PRE: 1 A*rs_out | 2 relu(A*rs_in+bias)*rs_out | 3 A*rs_in+bias
// WMAP: 0 W is [K x NOUT] row-major | 1 split map of Wp1[128x64]
template<int K, int NOUT, int NODES, int TX, int PRE, int WMAP>
__global__ __launch_bounds__(256) void gemm_k(
    const float* __restrict__ A, const float* __restrict__ W,
    const float* __restrict__ bias, float* __restrict__ C)
{
    constexpr int NPT = NOUT / TX;      // 4
    constexpr int TY  = 256 / TX;
    constexpr int RPT = NODES / TY;     // 8
    constexpr int KC  = 32;
    constexpr int KG  = KC / 4;
    constexpr int XSTR = NODES + 4;
    static_assert(NPT == 4 && RPT == 8, "blocking assumption");
    __shared__ __align__(16) float Ws[KC * NOUT];
    __shared__ __align__(16) float Xs[KC * XSTR];
    int tid = threadIdx.x;
    int tx = tid % TX, ty = tid / TX;
    int nb = blockIdx.x * NODES;

    float acc[RPT][NPT];
#pragma unroll
    for (int r = 0; r < RPT; r++)
#pragma unroll
        for (int c = 0; c < NPT; c++) acc[r][c] = 0.f;

    for (int p = 0; p < K / KC; p++) {
        for (int idx = tid * 4; idx < KC * NOUT; idx += 1024) {
            int kk = idx / NOUT, j = idx % NOUT;
            int k = p * KC + kk;
            float4 w;
            if (WMAP == 0) {
                w = *(const float4*)&W[(size_t)k * NOUT + j];
            } else {
                if (j < 64) w = *(const float4*)&W[k * 64 + j];
                else        w = *(const float4*)&W[(64 + k) * 64 + (j - 64)];
            }
            *(float4*)&Ws[kk * NOUT + j] = w;
        }
        for (int idx = tid; idx < NODES * KG; idx += 256) {
            int nl = idx / KG, kg = idx % KG;
            int n = nb + nl;
            int k = p * KC + kg * 4;
            float v0 = 0.f, v1 = 0.f, v2 = 0.f, v3 = 0.f;
            if (n < NN) {
                float4 t = *(const float4*)&A[(size_t)n * K + k];
                if (PRE == 1) {
                    float ro = g_rs_out[n];
                    v0 = t.x * ro; v1 = t.y * ro; v2 = t.z * ro; v3 = t.w * ro;
                } else if (PRE == 2) {
                    float ri = g_rs_in[n], ro = g_rs_out[n];
                    float4 bb = *(const float4*)&bias[k];
                    v0 = fmaxf(fmaf(t.x, ri, bb.x), 0.f) * ro;
                    v1 = fmaxf(fmaf(t.y, ri, bb.y), 0.f) * ro;
                    v2 = fmaxf(fmaf(t.z, ri, bb.z), 0.f) * ro;
                    v3 = fmaxf(fmaf(t.w, ri, bb.w), 0.f) * ro;
                } else {
                    float ri = g_rs_in[n];
                    float4 bb = *(const float4*)&bias[k];
                    v0 = fmaf(t.x, ri, bb.x);
                    v1 = fmaf(t.y, ri, bb.y);
                    v2 = fmaf(t.z, ri, bb.z);
                    v3 = fmaf(t.w, ri, bb.w);
                }
            }
            int kb = kg * 4;
            Xs[(kb + 0) * XSTR + nl] = v0;
            Xs[(kb + 1) * XSTR + nl] = v1;
            Xs[(kb + 2) * XSTR + nl] = v2;
            Xs[(kb + 3) * XSTR + nl] = v3;
        }
        __syncthreads();
#pragma unroll
        for (int kk = 0; kk < KC; kk++) {
            float4 w = *(const float4*)&Ws[kk * NOUT + tx * NPT];
            const float* xp = &Xs[kk * XSTR + ty * RPT];
            float4 x0 = *(const float4*)xp;
            float4 x1 = *(const float4*)(xp + 4);
            float wv[4] = { w.x, w.y, w.z, w.w };
            float xv[8] = { x0.x, x0.y, x0.z, x0.w, x1.x, x1.y, x1.z, x1.w };
#pragma unroll
            for (int r = 0; r < RPT; r++)
#pragma unroll
                for (int c = 0; c < NPT; c++) acc[r][c] = fmaf(xv[r], wv[c], acc[r][c]);
        }
        __syncthreads();
    }
#pragma unroll
    for (int r = 0; r < RPT; r++) {
        int n = nb + ty * RPT + r;
        if (n < NN) {
            float4 o = make_float4(acc[r][0], acc[r][1], acc[r][2], acc[r][3]);
            *(float4*)&C[(size_t)n * NOUT + tx * NPT] = o;
        }
    }
}

// ---------------- per-edge MLP: tensor-core phase B (3xTF32 mma.sync) ----------------
// Block: 128 threads (4 warps) handle 128 edges.
// Phase A: z1[e][k] = relu(pre_a[src][k] + pre_c[dst][k] + bp1[k]) -> smem k-major.
// Phase B: Z2 = relu(Z1 @ Wp2 + bp2) via m16n8k8 tf32 (hi*hi + lo*hi + hi*lo).
// Phase C: score = Z2 @ Wp3 + bp3; sigmoid.
__global__ __launch_bounds__(128) void edge_mlp_k(
    const float* __restrict__ Wp2, const float* __restrict__ bp1,
    const float* __restrict__ bp2, const float* __restrict__ Wp3,
    const float* __restrict__ bp3, float* __restrict__ out)
{
    __shared__ __align__(16) float z1s[64 * 132];   // k-major: z1s[k*132 + e]
    __shared__ __align__(16) float w2s[64 * 32];    // Wp2 row-major [k][n]
    __shared__ float b1s[64];
    __shared__ float b2s[32];
    __shared__ float w3s[32];
    __shared__ float b3s;
    int tid = threadIdx.x;

    for (int i = tid; i < 64 * 32; i += 128) w2s[i] = Wp2[i];
    if (tid < 64)       b1s[tid]      = bp1[tid];
    else if (tid < 96)  b2s[tid - 64] = bp2[tid - 64];
    else                w3s[tid - 96] = Wp3[tid - 96];
    if (tid == 0) b3s = bp3[0];

    // Phase A: one thread per edge
    int e = blockIdx.x * 128 + tid;   // NE % 128 == 0
    int s = g_src32[e], d = g_dst32[e];
    const float* ps = &g_pre[(size_t)s * 128];
    const float* pd = &g_pre[(size_t)d * 128 + 64];
    __syncthreads();
#pragma unroll
    for (int j = 0; j < 64; j += 4) {
        float4 a  = *(const float4*)&ps[j];
        float4 b  = *(const float4*)&pd[j];
        float4 bb = *(const float4*)&b1s[j];
        z1s[(j + 0) * 132 + tid] = fmaxf(a.x + b.x + bb.x, 0.f);
        z1s[(j + 1) * 132 + tid] = fmaxf(a.y + b.y + bb.y, 0.f);
        z1s[(j + 2) * 132 + tid] = fmaxf(a.z + b.z + bb.z, 0.f);
        z1s[(j + 3) * 132 + tid] = fmaxf(a.w + b.w + bb.w, 0.f);
    }
    __syncthreads();

    // Phase B: mma. Warp w covers edges [w*32, w*32+32): 2 row tiles of 16.
    int lane = tid & 31;
    int warp = tid >> 5;
    int g    = lane >> 2;   // 0..7
    int tig  = lane & 3;    // 0..3

    float acc[2][4][4];     // [rowtile][coltile][c0..c3]
#pragma unroll
    for (int rt = 0; rt < 2; rt++)
#pragma unroll
        for (int ct = 0; ct < 4; ct++)
#pragma unroll
            for (int q = 0; q < 4; q++) acc[rt][ct][q] = 0.f;

#pragma unroll
    for (int k8 = 0; k8 < 8; k8++) {
        int kb = k8 * 8;
        // B fragments (k rows kb+tig, kb+tig+4; n col = ct*8 + g), hi/lo split
        unsigned bhi[4][2], blo[4][2];
#pragma unroll
        for (int ct = 0; ct < 4; ct++) {
            int col = ct * 8 + g;
            float w0 = w2s[(kb + tig) * 32 + col];
            float w1 = w2s[(kb + tig + 4) * 32 + col];
            bhi[ct][0] = tf32_of(w0);
            bhi[ct][1] = tf32_of(w1);
            blo[ct][0] = tf32_of(w0 - __uint_as_float(bhi[ct][0]));
            blo[ct][1] = tf32_of(w1 - __uint_as_float(bhi[ct][1]));
        }
#pragma unroll
        for (int rt = 0; rt < 2; rt++) {
            int e0 = warp * 32 + rt * 16;
            // A fragments: A[row=edge, col=k]; conflict-free (4*tig+g permutation)
            float v0 = z1s[(kb + tig) * 132 + e0 + g];
            float v1 = z1s[(kb + tig) * 132 + e0 + g + 8];
            float v2 = z1s[(kb + tig + 4) * 132 + e0 + g];
            float v3 = z1s[(kb + tig + 4) * 132 + e0 + g + 8];
            unsigned ah0 = tf32_of(v0), ah1 = tf32_of(v1), ah2 = tf32_of(v2), ah3 = tf32_of(v3);
            unsigned al0 = tf32_of(v0 - __uint_as_float(ah0));
            unsigned al1 = tf32_of(v1 - __uint_as_float(ah1));
            unsigned al2 = tf32_of(v2 - __uint_as_float(ah2));
            unsigned al3 = tf32_of(v3 - __uint_as_float(ah3));
#pragma unroll
            for (int ct = 0; ct < 4; ct++) {
                mma_tf32(acc[rt][ct], ah0, ah1, ah2, ah3, bhi[ct][0], bhi[ct][1]);
                mma_tf32(acc[rt][ct], al0, al1, al2, al3, bhi[ct][0], bhi[ct][1]);
                mma_tf32(acc[rt][ct], ah0, ah1, ah2, ah3, blo[ct][0], blo[ct][1]);
            }
        }
    }

    // Phase C: relu + bias, dot with Wp3, reduce over tig group (4 lanes), sigmoid.
    // Thread holds: edge e0+g (c0,c1) and e0+g+8 (c2,c3) at cols ct*8 + 2*tig, +1.
#pragma unroll
    for (int rt = 0; rt < 2; rt++) {
        float pe = 0.f, po = 0.f;
#pragma unroll
        for (int ct = 0; ct < 4; ct++) {
            int c0 = ct * 8 + 2 * tig, c1 = c0 + 1;
            float bb0 = b2s[c0], bb1 = b2s[c1];
            float w0 = w3s[c0], w1 = w3s[c1];
            pe += fmaxf(acc[rt][ct][0] + bb0, 0.f) * w0 + fmaxf(acc[rt][ct][1] + bb1, 0.f) * w1;
            po += fmaxf(acc[rt][ct][2] + bb0, 0.f) * w0 + fmaxf(acc[rt][ct][3] + bb1, 0.f) * w1;
        }
        pe += __shfl_down_sync(0xffffffffu, pe, 2, 4);
        pe += __shfl_down_sync(0xffffffffu, pe, 1, 4);
        po += __shfl_down_sync(0xffffffffu, po, 2, 4);
        po += __shfl_down_sync(0xffffffffu, po, 1, 4);
        if (tig == 0) {
            int ebase = blockIdx.x * 128 + warp * 32 + rt * 16;
            out[ebase + g]     = 1.f / (1.f + expf(-(pe + b3s)));
            out[ebase + g + 8] = 1.f / (1.f + expf(-(po + b3s)));
        }
    }
}

// ---------------- launch ----------------
extern "C" void kernel_launch(void* const* d_in, const int* in_sizes, int n_in,
                              void* d_out, int out_size) {
    const float* x   = (const float*)d_in[0];
    const void*  src = d_in[1];
    const void*  dst = d_in[2];
    const float* W1  = (const float*)d_in[3];
    const float* b1  = (const float*)d_in[4];
    const float* W2  = (const float*)d_in[5];
    const float* b2  = (const float*)d_in[6];
    const float* Wp1 = (const float*)d_in[7];
    const float* bp1 = (const float*)d_in[8];
    const float* Wp2 = (const float*)d_in[9];
    const float* bp2 = (const float*)d_in[10];
    const float* Wp3 = (const float*)d_in[11];
    const float* bp3 = (const float*)d_in[12];
    float* out = (float*)d_out;

    float *h1tmp, *agg1, *h2tmp, *agg2, *pre;
    cudaGetSymbolAddress((void**)&h1tmp, g_h1tmp);
    cudaGetSymbolAddress((void**)&agg1,  g_agg1);
    cudaGetSymbolAddress((void**)&h2tmp, g_h2tmp);
    cudaGetSymbolAddress((void**)&agg2,  g_agg2);
    cudaGetSymbolAddress((void**)&pre,   g_pre);

    zero_k<<<512, 256>>>(src);
    convert_deg_k<<<NE / 256, 256>>>(src, dst);
    scanA_k<<<NBLK_SCAN, 1024>>>();
    scanB_k<<<1, 128>>>();
    scanC_k<<<(NN + 255) / 256, 256>>>();
    bin_k<<<NE / 256, 256>>>();

    gemm_k<128, 128, 64, 32, 1, 0><<<(NN + 63) / 64, 256>>>(x, W1, b1, h1tmp);
    agg_k<128><<<(NN * 32 + 255) / 256, 256>>>(h1tmp, agg1);

    gemm_k<128, 64, 128, 16, 2, 0><<<(NN + 127) / 128, 256>>>(agg1, W2, b1, h2tmp);
    agg_k<64><<<(NN * 32 + 255) / 256, 256>>>(h2tmp, agg2);

    gemm_k<64, 128, 64, 32, 3, 1><<<(NN + 63) / 64, 256>>>(agg2, Wp1, b2, pre);

    edge_mlp_k<<<NE / 128, 128>>>(Wp2, bp1, bp2, Wp3, bp3, out);
}

// round 12
// speedup vs baseline: 1.1560x; 1.1560x over previous
#include <cuda_runtime.h>
#include <math.h>

#define NN 100000
#define NE 1600000
#define NBLK_SCAN 98   // ceil(NN/1024)

// ---------------- device scratch (no allocations allowed) ----------------
__device__ int   g_is64;
__device__ int   g_src32[NE];
__device__ int   g_dst32[NE];
__device__ int   g_deg_out[NN];
__device__ int   g_deg_in[NN];
__device__ float g_rs_out[NN];
__device__ float g_rs_in[NN];
__device__ int   g_ptr[NN];        // CSR row offsets (by dst)
__device__ int   g_fill[NN];       // binning cursors
__device__ int   g_bsum[128];      // scan block sums
__device__ int   g_csr_src[NE];    // src node per CSR slot
__device__ int   g_csr_dst[NE];    // dst node per CSR slot
__device__ int   g_csr_eid[NE];    // original edge id per CSR slot
__device__ float g_h1tmp[(size_t)NN * 128];
__device__ float g_agg1 [(size_t)NN * 128];
__device__ float g_h2tmp[(size_t)NN * 64];
__device__ float g_agg2 [(size_t)NN * 64];
__device__ float g_pre  [(size_t)NN * 128];   // [:,0:64]=a_pre(src), [:,64:128]=c_pre(dst)+bp1

// ---------------- zero degree counters + index-width detect ----------------
__global__ void zero_k(const void* src) {
    int tid = blockIdx.x * blockDim.x + threadIdx.x;
    int stride = gridDim.x * blockDim.x;
    for (int i = tid; i < NN; i += stride) { g_deg_out[i] = 0; g_deg_in[i] = 0; }
    if (blockIdx.x == 0 && threadIdx.x < 32) {
        const long long* p = (const long long*)src;
        bool ok = true;
        for (int i = threadIdx.x; i < 256; i += 32) {
            long long v = p[i];
            if (v < 0 || v >= NN) ok = false;
        }
        unsigned m = __ballot_sync(0xffffffffu, ok);
        if (threadIdx.x == 0) g_is64 = (m == 0xffffffffu) ? 1 : 0;
    }
}

// ---------------- normalize indices to int32 + degree histogram ----------------
__global__ void convert_deg_k(const void* srcp, const void* dstp) {
    int e = blockIdx.x * blockDim.x + threadIdx.x;
    if (e >= NE) return;
    int s, d;
    if (g_is64) {
        s = (int)((const long long*)srcp)[e];
        d = (int)((const long long*)dstp)[e];
    } else {
        s = ((const int*)srcp)[e];
        d = ((const int*)dstp)[e];
    }
    g_src32[e] = s;
    g_dst32[e] = d;
    atomicAdd(&g_deg_out[s], 1);
    atomicAdd(&g_deg_in[d], 1);
}

// ---------------- rsqrt of degrees (default stream; gemm1 depends on it) ----------------
__global__ void rsqrt_k() {
    int n = blockIdx.x * 256 + threadIdx.x;
    if (n >= NN) return;
    g_rs_out[n] = rsqrtf(fmaxf((float)g_deg_out[n], 1.f));
    g_rs_in[n]  = rsqrtf(fmaxf((float)g_deg_in[n],  1.f));
}

// ---------------- exclusive scan of deg_in ----------------
__global__ __launch_bounds__(1024) void scanA_k() {
    int n = blockIdx.x * 1024 + threadIdx.x;
    int v = (n < NN) ? g_deg_in[n] : 0;
    int lane = threadIdx.x & 31, wid = threadIdx.x >> 5;
    int x = v;
#pragma unroll
    for (int o = 1; o < 32; o <<= 1) {
        int y = __shfl_up_sync(0xffffffffu, x, o);
        if (lane >= o) x += y;
    }
    __shared__ int wsum[32];
    if (lane == 31) wsum[wid] = x;
    __syncthreads();
    if (wid == 0) {
        int t = wsum[lane];
#pragma unroll
        for (int o = 1; o < 32; o <<= 1) {
            int y = __shfl_up_sync(0xffffffffu, t, o);
            if (lane >= o) t += y;
        }
        wsum[lane] = t;
    }
    __syncthreads();
    int base = (wid > 0) ? wsum[wid - 1] : 0;
    int excl = base + x - v;
    if (n < NN) g_ptr[n] = excl;
    if (threadIdx.x == 1023) g_bsum[blockIdx.x] = excl + v;
}

__global__ void scanB_k() {
    int i = threadIdx.x, lane = i & 31, w = i >> 5;
    int v = (i < NBLK_SCAN) ? g_bsum[i] : 0;
    int x = v;
#pragma unroll
    for (int o = 1; o < 32; o <<= 1) {
        int y = __shfl_up_sync(0xffffffffu, x, o);
        if (lane >= o) x += y;
    }
    __shared__ int ws[4];
    if (lane == 31) ws[w] = x;
    __syncthreads();
    int off = 0;
    for (int k = 0; k < w; k++) off += ws[k];
    if (i < NBLK_SCAN) g_bsum[i] = off + x - v;
}

// fixup + init fill cursors
__global__ void scanC_k() {
    int n = blockIdx.x * 256 + threadIdx.x;
    if (n >= NN) return;
    int p = g_ptr[n] + g_bsum[n >> 10];
    g_ptr[n] = p;
    g_fill[n] = p;
}

// ---------------- bin edges by dst (records src, dst, original eid) ----------------
__global__ void bin_k() {
    int e = blockIdx.x * 256 + threadIdx.x;
    if (e >= NE) return;
    int d = g_dst32[e];
    int slot = atomicAdd(&g_fill[d], 1);
    g_csr_src[slot] = g_src32[e];
    g_csr_dst[slot] = d;
    g_csr_eid[slot] = e;
}

// ---------------- CSR aggregation: one warp per dst node ----------------
template<int DIM>
__global__ __launch_bounds__(256) void agg_k(const float* __restrict__ H,
                                             float* __restrict__ AG) {
    int warp = (blockIdx.x * 256 + threadIdx.x) >> 5;
    if (warp >= NN) return;
    int lane = threadIdx.x & 31;
    int ptr = g_ptr[warp];
    int deg = g_deg_in[warp];
    if (DIM == 128) {
        float4 acc = make_float4(0.f, 0.f, 0.f, 0.f);
        for (int base = 0; base < deg; base += 32) {
            int cnt = min(32, deg - base);
            int idx = (base + lane < deg) ? g_csr_src[ptr + base + lane] : 0;
            for (int j = 0; j < cnt; j++) {
                int s = __shfl_sync(0xffffffffu, idx, j);
                float4 v = *(const float4*)&H[(size_t)s * 128 + lane * 4];
                acc.x += v.x; acc.y += v.y; acc.z += v.z; acc.w += v.w;
            }
        }
        *(float4*)&AG[(size_t)warp * 128 + lane * 4] = acc;
    } else {
        float2 acc = make_float2(0.f, 0.f);
        for (int base = 0; base < deg; base += 32) {
            int cnt = min(32, deg - base);
            int idx = (base + lane < deg) ? g_csr_src[ptr + base + lane] : 0;
            for (int j = 0; j < cnt; j++) {
                int s = __shfl_sync(0xffffffffu, idx, j);
                float2 v = *(const float2*)&H[(size_t)s * 64 + lane * 2];
                acc.x += v.x; acc.y += v.y;
            }
        }
        *(float2*)&AG[(size_t)warp * 64 + lane * 2] = acc;
    }
}

// ---------------- node GEMM, k-major activation tile, scalar FFMA (R5-proven) ----------------
// PRE: 1 A*rs_out | 2 relu(A*rs_in+bias)*rs_out | 3 A*rs_in+bias
// WMAP: 0 W is [K x NOUT] row-major | 1 split map of Wp1[128x64]; epilogue adds
//       ebias[j-64] to columns j>=64 (folds bp1 into the dst half of g_pre).
template<int K, int NOUT, int NODES, int TX, int PRE, int WMAP>
__global__ __launch_bounds__(256) void gemm_k(
    const float* __restrict__ A, const float* __restrict__ W,
    const float* __restrict__ bias, const float* __restrict__ ebias,
    float* __restrict__ C)
{
    constexpr int NPT = NOUT / TX;      // 4
    constexpr int TY  = 256 / TX;
    constexpr int RPT = NODES / TY;     // 8
    constexpr int KC  = 32;
    constexpr int KG  = KC / 4;
    constexpr int XSTR = NODES + 4;
    static_assert(NPT == 4 && RPT == 8, "blocking assumption");
    __shared__ __align__(16) float Ws[KC * NOUT];
    __shared__ __align__(16) float Xs[KC * XSTR];
    int tid = threadIdx.x;
    int tx = tid % TX, ty = tid / TX;
    int nb = blockIdx.x * NODES;

    float acc[RPT][NPT];
#pragma unroll
    for (int r = 0; r < RPT; r++)
#pragma unroll
        for (int c = 0; c < NPT; c++) acc[r][c] = 0.f;

    for (int p = 0; p < K / KC; p++) {
        for (int idx = tid * 4; idx < KC * NOUT; idx += 1024) {
            int kk = idx / NOUT, j = idx % NOUT;
            int k = p * KC + kk;
            float4 w;
            if (WMAP == 0) {
                w = *(const float4*)&W[(size_t)k * NOUT + j];
            } else {
                if (j < 64) w = *(const float4*)&W[k * 64 + j];
                else        w = *(const float4*)&W[(64 + k) * 64 + (j - 64)];
            }
            *(float4*)&Ws[kk * NOUT + j] = w;
        }
        for (int idx = tid; idx < NODES * KG; idx += 256) {
            int nl = idx / KG, kg = idx % KG;
            int n = nb + nl;
            int k = p * KC + kg * 4;
            float v0 = 0.f, v1 = 0.f, v2 = 0.f, v3 = 0.f;
            if (n < NN) {
                float4 t = *(const float4*)&A[(size_t)n * K + k];
                if (PRE == 1) {
                    float ro = g_rs_out[n];
                    v0 = t.x * ro; v1 = t.y * ro; v2 = t.z * ro; v3 = t.w * ro;
                } else if (PRE == 2) {
                    float ri = g_rs_in[n], ro = g_rs_out[n];
                    float4 bb = *(const float4*)&bias[k];
                    v0 = fmaxf(fmaf(t.x, ri, bb.x), 0.f) * ro;
                    v1 = fmaxf(fmaf(t.y, ri, bb.y), 0.f) * ro;
                    v2 = fmaxf(fmaf(t.z, ri, bb.z), 0.f) * ro;
                    v3 = fmaxf(fmaf(t.w, ri, bb.w), 0.f) * ro;
                } else {
                    float ri = g_rs_in[n];
                    float4 bb = *(const float4*)&bias[k];
                    v0 = fmaf(t.x, ri, bb.x);
                    v1 = fmaf(t.y, ri, bb.y);
                    v2 = fmaf(t.z, ri, bb.z);
                    v3 = fmaf(t.w, ri, bb.w);
                }
            }
            int kb = kg * 4;
            Xs[(kb + 0) * XSTR + nl] = v0;
            Xs[(kb + 1) * XSTR + nl] = v1;
            Xs[(kb + 2) * XSTR + nl] = v2;
            Xs[(kb + 3) * XSTR + nl] = v3;
        }
        __syncthreads();
#pragma unroll
        for (int kk = 0; kk < KC; kk++) {
            float4 w = *(const float4*)&Ws[kk * NOUT + tx * NPT];
            const float* xp = &Xs[kk * XSTR + ty * RPT];
            float4 x0 = *(const float4*)xp;
            float4 x1 = *(const float4*)(xp + 4);
            float wv[4] = { w.x, w.y, w.z, w.w };
            float xv[8] = { x0.x, x0.y, x0.z, x0.w, x1.x, x1.y, x1.z, x1.w };
#pragma unroll
            for (int r = 0; r < RPT; r++)
#pragma unroll
                for (int c = 0; c < NPT; c++) acc[r][c] = fmaf(xv[r], wv[c], acc[r][c]);
        }
        __syncthreads();
    }
    float4 eb = make_float4(0.f, 0.f, 0.f, 0.f);
    if (WMAP == 1 && tx >= 16) eb = *(const float4*)&ebias[tx * 4 - 64];
#pragma unroll
    for (int r = 0; r < RPT; r++) {
        int n = nb + ty * RPT + r;
        if (n < NN) {
            float4 o = make_float4(acc[r][0] + eb.x, acc[r][1] + eb.y,
                                   acc[r][2] + eb.z, acc[r][3] + eb.w);
            *(float4*)&C[(size_t)n * NOUT + tx * NPT] = o;
        }
    }
}

// ---------------- per-edge MLP in CSR(dst) order ----------------
// 128 threads per block, 128 edges. dst-half gathers hit duplicate addresses
// within a warp (edges sorted by dst) -> LDG dedup. Output scattered via eid.
__global__ __launch_bounds__(128) void edge_mlp_k(
    const float* __restrict__ Wp2, const float* __restrict__ bp2,
    const float* __restrict__ Wp3, const float* __restrict__ bp3,
    float* __restrict__ out)
{
    __shared__ __align__(16) float z1s[64 * 132];   // k-major: z1s[k*132 + e]
    __shared__ __align__(16) float w2s[64 * 32];
    __shared__ float b2s[32];
    __shared__ float w3s[32];
    __shared__ float b3s;
    __shared__ int   eids[128];
    int tid = threadIdx.x;

    for (int i = tid; i < 64 * 32; i += 128) w2s[i] = Wp2[i];
    if (tid < 32)       b2s[tid]      = bp2[tid];
    else if (tid < 64)  w3s[tid - 32] = Wp3[tid - 32];
    if (tid == 64) b3s = bp3[0];

    // Phase A: one thread per CSR slot; z1 = relu(a_pre[s] + (c_pre[d]+bp1))
    int slot = blockIdx.x * 128 + tid;   // NE % 128 == 0
    int s = g_csr_src[slot], d = g_csr_dst[slot];
    eids[tid] = g_csr_eid[slot];
    const float* ps = &g_pre[(size_t)s * 128];
    const float* pd = &g_pre[(size_t)d * 128 + 64];
#pragma unroll
    for (int j = 0; j < 64; j += 4) {
        float4 a = *(const float4*)&ps[j];
        float4 c = *(const float4*)&pd[j];
        z1s[(j + 0) * 132 + tid] = fmaxf(a.x + c.x, 0.f);
        z1s[(j + 1) * 132 + tid] = fmaxf(a.y + c.y, 0.f);
        z1s[(j + 2) * 132 + tid] = fmaxf(a.z + c.z, 0.f);
        z1s[(j + 3) * 132 + tid] = fmaxf(a.w + c.w, 0.f);
    }
    __syncthreads();

    // Phase B: 8 edges x 4 cols per thread (scalar FFMA, R5-proven balance)
    int tx = tid & 7;    // col group (4 cols)
    int ey = tid >> 3;   // edge group (8 edges): 16 groups * 8 = 128 edges
    float acc[8][4];
#pragma unroll
    for (int r = 0; r < 8; r++)
#pragma unroll
        for (int c = 0; c < 4; c++) acc[r][c] = 0.f;

#pragma unroll 4
    for (int k = 0; k < 64; k++) {
        float4 w  = *(const float4*)&w2s[k * 32 + tx * 4];
        float4 z0 = *(const float4*)&z1s[k * 132 + ey * 8];
        float4 z1 = *(const float4*)&z1s[k * 132 + ey * 8 + 4];
        float ww[4] = { w.x, w.y, w.z, w.w };
        float zz[8] = { z0.x, z0.y, z0.z, z0.w, z1.x, z1.y, z1.z, z1.w };
#pragma unroll
        for (int r = 0; r < 8; r++)
#pragma unroll
            for (int c = 0; c < 4; c++) acc[r][c] = fmaf(zz[r], ww[c], acc[r][c]);
    }

    // Phase C: relu + partial dot with Wp3, reduce across the 8 col-groups
    float4 w3  = *(const float4*)&w3s[tx * 4];
    float4 bb2 = *(const float4*)&b2s[tx * 4];
    float pscore[8];
#pragma unroll
    for (int r = 0; r < 8; r++) {
        float q0 = fmaxf(acc[r][0] + bb2.x, 0.f);
        float q1 = fmaxf(acc[r][1] + bb2.y, 0.f);
        float q2 = fmaxf(acc[r][2] + bb2.z, 0.f);
        float q3 = fmaxf(acc[r][3] + bb2.w, 0.f);
        pscore[r] = q0 * w3.x + q1 * w3.y + q2 * w3.z + q3 * w3.w;
    }
#pragma unroll
    for (int off = 4; off >= 1; off >>= 1)
#pragma unroll
        for (int r = 0; r < 8; r++)
            pscore[r] += __shfl_down_sync(0xffffffffu, pscore[r], off, 8);

    if (tx == 0) {
#pragma unroll
        for (int r = 0; r < 8; r++) {
            float sc = pscore[r] + b3s;
            out[eids[ey * 8 + r]] = 1.f / (1.f + expf(-sc));
        }
    }
}

// ---------------- launch ----------------
extern "C" void kernel_launch(void* const* d_in, const int* in_sizes, int n_in,
                              void* d_out, int out_size) {
    const float* x   = (const float*)d_in[0];
    const void*  src = d_in[1];
    const void*  dst = d_in[2];
    const float* W1  = (const float*)d_in[3];
    const float* b1  = (const float*)d_in[4];
    const float* W2  = (const float*)d_in[5];
    const float* b2  = (const float*)d_in[6];
    const float* Wp1 = (const float*)d_in[7];
    const float* bp1 = (const float*)d_in[8];
    const float* Wp2 = (const float*)d_in[9];
    const float* bp2 = (const float*)d_in[10];
    const float* Wp3 = (const float*)d_in[11];
    const float* bp3 = (const float*)d_in[12];
    float* out = (float*)d_out;

    float *h1tmp, *agg1, *h2tmp, *agg2, *pre;
    cudaGetSymbolAddress((void**)&h1tmp, g_h1tmp);
    cudaGetSymbolAddress((void**)&agg1,  g_agg1);
    cudaGetSymbolAddress((void**)&h2tmp, g_h2tmp);
    cudaGetSymbolAddress((void**)&agg2,  g_agg2);
    cudaGetSymbolAddress((void**)&pre,   g_pre);

    // side stream + events, created on the first (non-captured) call
    static cudaStream_t s1 = nullptr;
    static cudaEvent_t evA = nullptr, evB = nullptr;
    if (s1 == nullptr) {
        cudaStreamCreateWithFlags(&s1, cudaStreamNonBlocking);
        cudaEventCreateWithFlags(&evA, cudaEventDisableTiming);
        cudaEventCreateWithFlags(&evB, cudaEventDisableTiming);
    }

    zero_k<<<512, 256>>>(src);
    convert_deg_k<<<NE / 256, 256>>>(src, dst);

    // fork: CSR build (scan + bin) on s1, overlapped with rsqrt + gemm1
    cudaEventRecord(evA, 0);
    cudaStreamWaitEvent(s1, evA, 0);
    scanA_k<<<NBLK_SCAN, 1024, 0, s1>>>();
    scanB_k<<<1, 128, 0, s1>>>();
    scanC_k<<<(NN + 255) / 256, 256, 0, s1>>>();
    bin_k<<<NE / 256, 256, 0, s1>>>();
    cudaEventRecord(evB, s1);

    rsqrt_k<<<(NN + 255) / 256, 256>>>();
    gemm_k<128, 128, 64, 32, 1, 0><<<(NN + 63) / 64, 256>>>(x, W1, b1, nullptr, h1tmp);

    // join before aggregation needs the CSR
    cudaStreamWaitEvent(0, evB, 0);
    agg_k<128><<<(NN * 32 + 255) / 256, 256>>>(h1tmp, agg1);

    gemm_k<128, 64, 128, 16, 2, 0><<<(NN + 127) / 128, 256>>>(agg1, W2, b1, nullptr, h2tmp);
    agg_k<64><<<(NN * 32 + 255) / 256, 256>>>(h2tmp, agg2);

    // pre = (agg2*rs_in + b2) @ [Wp1_top | Wp1_bot]; +bp1 folded into cols 64..127
    gemm_k<64, 128, 64, 32, 3, 1><<<(NN + 63) / 64, 256>>>(agg2, Wp1, b2, bp1, pre);

    // per-edge MLP + sigmoid, CSR(dst) order, scatter by eid
    edge_mlp_k<<<NE / 128, 128>>>(Wp2, bp2, Wp3, bp3, out);
}

// round 13
// speedup vs baseline: 1.2056x; 1.0428x over previous
#include <cuda_runtime.h>
#include <cuda_fp16.h>
#include <math.h>

#define NN 100000
#define NE 1600000
#define NBLK_SCAN 98   // ceil(NN/1024)

// ---------------- device scratch (no allocations allowed) ----------------
__device__ int    g_is64;
__device__ int    g_src32[NE];
__device__ int    g_dst32[NE];
__device__ int    g_deg_out[NN];
__device__ int    g_deg_in[NN];
__device__ int    g_ptr[NN];        // CSR row offsets (by dst)
__device__ int    g_fill[NN];       // binning cursors
__device__ int    g_bsum[128];      // scan block sums
__device__ int    g_csr_src[NE];    // src node per CSR slot
__device__ int    g_csr_dst[NE];    // dst node per CSR slot
__device__ int    g_csr_eid[NE];    // original edge id per CSR slot
__device__ __half g_h1tmp[(size_t)NN * 128];   // fp16: halves agg1 gather traffic
__device__ float  g_agg1 [(size_t)NN * 128];
__device__ __half g_h2tmp[(size_t)NN * 64];    // fp16: halves agg2 gather traffic
__device__ float  g_agg2 [(size_t)NN * 64];
__device__ float  g_pre  [(size_t)NN * 128];   // [:,0:64]=a_pre(src), [:,64:128]=c_pre(dst)+bp1

__device__ __forceinline__ float rs_of(int deg) {
    return rsqrtf(fmaxf((float)deg, 1.f));
}

// ---------------- zero degree counters + index-width detect ----------------
__global__ void zero_k(const void* src) {
    int tid = blockIdx.x * blockDim.x + threadIdx.x;
    int stride = gridDim.x * blockDim.x;
    for (int i = tid; i < NN; i += stride) { g_deg_out[i] = 0; g_deg_in[i] = 0; }
    if (blockIdx.x == 0 && threadIdx.x < 32) {
        const long long* p = (const long long*)src;
        bool ok = true;
        for (int i = threadIdx.x; i < 256; i += 32) {
            long long v = p[i];
            if (v < 0 || v >= NN) ok = false;
        }
        unsigned m = __ballot_sync(0xffffffffu, ok);
        if (threadIdx.x == 0) g_is64 = (m == 0xffffffffu) ? 1 : 0;
    }
}

// ---------------- normalize indices to int32 + degree histogram ----------------
__global__ void convert_deg_k(const void* srcp, const void* dstp) {
    int e = blockIdx.x * blockDim.x + threadIdx.x;
    if (e >= NE) return;
    int s, d;
    if (g_is64) {
        s = (int)((const long long*)srcp)[e];
        d = (int)((const long long*)dstp)[e];
    } else {
        s = ((const int*)srcp)[e];
        d = ((const int*)dstp)[e];
    }
    g_src32[e] = s;
    g_dst32[e] = d;
    atomicAdd(&g_deg_out[s], 1);
    atomicAdd(&g_deg_in[d], 1);
}

// ---------------- exclusive scan of deg_in ----------------
__global__ __launch_bounds__(1024) void scanA_k() {
    int n = blockIdx.x * 1024 + threadIdx.x;
    int v = (n < NN) ? g_deg_in[n] : 0;
    int lane = threadIdx.x & 31, wid = threadIdx.x >> 5;
    int x = v;
#pragma unroll
    for (int o = 1; o < 32; o <<= 1) {
        int y = __shfl_up_sync(0xffffffffu, x, o);
        if (lane >= o) x += y;
    }
    __shared__ int wsum[32];
    if (lane == 31) wsum[wid] = x;
    __syncthreads();
    if (wid == 0) {
        int t = wsum[lane];
#pragma unroll
        for (int o = 1; o < 32; o <<= 1) {
            int y = __shfl_up_sync(0xffffffffu, t, o);
            if (lane >= o) t += y;
        }
        wsum[lane] = t;
    }
    __syncthreads();
    int base = (wid > 0) ? wsum[wid - 1] : 0;
    int excl = base + x - v;
    if (n < NN) g_ptr[n] = excl;
    if (threadIdx.x == 1023) g_bsum[blockIdx.x] = excl + v;
}

__global__ void scanB_k() {
    int i = threadIdx.x, lane = i & 31, w = i >> 5;
    int v = (i < NBLK_SCAN) ? g_bsum[i] : 0;
    int x = v;
#pragma unroll
    for (int o = 1; o < 32; o <<= 1) {
        int y = __shfl_up_sync(0xffffffffu, x, o);
        if (lane >= o) x += y;
    }
    __shared__ int ws[4];
    if (lane == 31) ws[w] = x;
    __syncthreads();
    int off = 0;
    for (int k = 0; k < w; k++) off += ws[k];
    if (i < NBLK_SCAN) g_bsum[i] = off + x - v;
}

// fixup + init fill cursors
__global__ void scanC_k() {
    int n = blockIdx.x * 256 + threadIdx.x;
    if (n >= NN) return;
    int p = g_ptr[n] + g_bsum[n >> 10];
    g_ptr[n] = p;
    g_fill[n] = p;
}

// ---------------- bin edges by dst (records src, dst, original eid) ----------------
__global__ void bin_k() {
    int e = blockIdx.x * 256 + threadIdx.x;
    if (e >= NE) return;
    int d = g_dst32[e];
    int slot = atomicAdd(&g_fill[d], 1);
    g_csr_src[slot] = g_src32[e];
    g_csr_dst[slot] = d;
    g_csr_eid[slot] = e;
}

// ---------------- CSR aggregation (fp16 input rows, fp32 accum) ----------------
template<int DIM>
__global__ __launch_bounds__(256) void agg_k(const __half* __restrict__ H,
                                             float* __restrict__ AG) {
    int warp = (blockIdx.x * 256 + threadIdx.x) >> 5;
    if (warp >= NN) return;
    int lane = threadIdx.x & 31;
    int ptr = g_ptr[warp];
    int deg = g_deg_in[warp];
    if (DIM == 128) {
        float4 acc = make_float4(0.f, 0.f, 0.f, 0.f);
        for (int base = 0; base < deg; base += 32) {
            int cnt = min(32, deg - base);
            int idx = (base + lane < deg) ? g_csr_src[ptr + base + lane] : 0;
            for (int j = 0; j < cnt; j++) {
                int s = __shfl_sync(0xffffffffu, idx, j);
                uint2 u = *(const uint2*)&H[(size_t)s * 128 + lane * 4];
                float2 f0 = __half22float2(*(__half2*)&u.x);
                float2 f1 = __half22float2(*(__half2*)&u.y);
                acc.x += f0.x; acc.y += f0.y; acc.z += f1.x; acc.w += f1.y;
            }
        }
        *(float4*)&AG[(size_t)warp * 128 + lane * 4] = acc;
    } else {
        float2 acc = make_float2(0.f, 0.f);
        for (int base = 0; base < deg; base += 32) {
            int cnt = min(32, deg - base);
            int idx = (base + lane < deg) ? g_csr_src[ptr + base + lane] : 0;
            for (int j = 0; j < cnt; j++) {
                int s = __shfl_sync(0xffffffffu, idx, j);
                unsigned u = *(const unsigned*)&H[(size_t)s * 64 + lane * 2];
                float2 f0 = __half22float2(*(__half2*)&u);
                acc.x += f0.x; acc.y += f0.y;
            }
        }
        *(float2*)&AG[(size_t)warp * 64 + lane * 2] = acc;
    }
}

// ---------------- node GEMM, k-major activation tile, scalar FFMA ----------------
// PRE: 1 A*rs(deg_out) | 2 relu(A*rs(deg_in)+bias)*rs(deg_out) | 3 A*rs(deg_in)+bias
// WMAP: 0 W is [K x NOUT] row-major | 1 split map of Wp1[128x64]; epilogue adds
//       ebias[j-64] to columns j>=64. OT: float or __half output.
template<int K, int NOUT, int NODES, int TX, int PRE, int WMAP, typename OT>
__global__ __launch_bounds__(256) void gemm_k(
    const float* __restrict__ A, const float* __restrict__ W,
    const float* __restrict__ bias, const float* __restrict__ ebias,
    OT* __restrict__ C)
{
    constexpr int NPT = NOUT / TX;      // 4
    constexpr int TY  = 256 / TX;
    constexpr int RPT = NODES / TY;     // 8
    constexpr int KC  = 32;
    constexpr int KG  = KC / 4;
    constexpr int XSTR = NODES + 4;
    static_assert(NPT == 4 && RPT == 8, "blocking assumption");
    __shared__ __align__(16) float Ws[KC * NOUT];
    __shared__ __align__(16) float Xs[KC * XSTR];
    int tid = threadIdx.x;
    int tx = tid % TX, ty = tid / TX;
    int nb = blockIdx.x * NODES;

    float acc[RPT][NPT];
#pragma unroll
    for (int r = 0; r < RPT; r++)
#pragma unroll
        for (int c = 0; c < NPT; c++) acc[r][c] = 0.f;

    for (int p = 0; p < K / KC; p++) {
        for (int idx = tid * 4; idx < KC * NOUT; idx += 1024) {
            int kk = idx / NOUT, j = idx % NOUT;
            int k = p * KC + kk;
            float4 w;
            if (WMAP == 0) {
                w = *(const float4*)&W[(size_t)k * NOUT + j];
            } else {
                if (j < 64) w = *(const float4*)&W[k * 64 + j];
                else        w = *(const float4*)&W[(64 + k) * 64 + (j - 64)];
            }
            *(float4*)&Ws[kk * NOUT + j] = w;
        }
        for (int idx = tid; idx < NODES * KG; idx += 256) {
            int nl = idx / KG, kg = idx % KG;
            int n = nb + nl;
            int k = p * KC + kg * 4;
            float v0 = 0.f, v1 = 0.f, v2 = 0.f, v3 = 0.f;
            if (n < NN) {
                float4 t = *(const float4*)&A[(size_t)n * K + k];
                if (PRE == 1) {
                    float ro = rs_of(g_deg_out[n]);
                    v0 = t.x * ro; v1 = t.y * ro; v2 = t.z * ro; v3 = t.w * ro;
                } else if (PRE == 2) {
                    float ri = rs_of(g_deg_in[n]), ro = rs_of(g_deg_out[n]);
                    float4 bb = *(const float4*)&bias[k];
                    v0 = fmaxf(fmaf(t.x, ri, bb.x), 0.f) * ro;
                    v1 = fmaxf(fmaf(t.y, ri, bb.y), 0.f) * ro;
                    v2 = fmaxf(fmaf(t.z, ri, bb.z), 0.f) * ro;
                    v3 = fmaxf(fmaf(t.w, ri, bb.w), 0.f) * ro;
                } else {
                    float ri = rs_of(g_deg_in[n]);
                    float4 bb = *(const float4*)&bias[k];
                    v0 = fmaf(t.x, ri, bb.x);
                    v1 = fmaf(t.y, ri, bb.y);
                    v2 = fmaf(t.z, ri, bb.z);
                    v3 = fmaf(t.w, ri, bb.w);
                }
            }
            int kb = kg * 4;
            Xs[(kb + 0) * XSTR + nl] = v0;
            Xs[(kb + 1) * XSTR + nl] = v1;
            Xs[(kb + 2) * XSTR + nl] = v2;
            Xs[(kb + 3) * XSTR + nl] = v3;
        }
        __syncthreads();
#pragma unroll
        for (int kk = 0; kk < KC; kk++) {
            float4 w = *(const float4*)&Ws[kk * NOUT + tx * NPT];
            const float* xp = &Xs[kk * XSTR + ty * RPT];
            float4 x0 = *(const float4*)xp;
            float4 x1 = *(const float4*)(xp + 4);
            float wv[4] = { w.x, w.y, w.z, w.w };
            float xv[8] = { x0.x, x0.y, x0.z, x0.w, x1.x, x1.y, x1.z, x1.w };
#pragma unroll
            for (int r = 0; r < RPT; r++)
#pragma unroll
                for (int c = 0; c < NPT; c++) acc[r][c] = fmaf(xv[r], wv[c], acc[r][c]);
        }
        __syncthreads();
    }
    float4 eb = make_float4(0.f, 0.f, 0.f, 0.f);
    if (WMAP == 1 && tx >= 16) eb = *(const float4*)&ebias[tx * 4 - 64];
#pragma unroll
    for (int r = 0; r < RPT; r++) {
        int n = nb + ty * RPT + r;
        if (n < NN) {
            if (sizeof(OT) == 2) {
                __half2 p0 = __floats2half2_rn(acc[r][0], acc[r][1]);
                __half2 p1 = __floats2half2_rn(acc[r][2], acc[r][3]);
                unsigned u0 = *reinterpret_cast<unsigned*>(&p0);
                unsigned u1 = *reinterpret_cast<unsigned*>(&p1);
                *(uint2*)&C[(size_t)n * NOUT + tx * NPT] = make_uint2(u0, u1);
            } else {
                float4 o = make_float4(acc[r][0] + eb.x, acc[r][1] + eb.y,
                                       acc[r][2] + eb.z, acc[r][3] + eb.w);
                *(float4*)&C[(size_t)n * NOUT + tx * NPT] = o;
            }
        }
    }
}

// ---------------- per-edge MLP in CSR(dst) order ----------------
__global__ __launch_bounds__(128) void edge_mlp_k(
    const float* __restrict__ Wp2, const float* __restrict__ bp2,
    const float* __restrict__ Wp3, const float* __restrict__ bp3,
    float* __restrict__ out)
{
    __shared__ __align__(16) float z1s[64 * 132];   // k-major: z1s[k*132 + e]
    __shared__ __align__(16) float w2s[64 * 32];
    __shared__ float b2s[32];
    __shared__ float w3s[32];
    __shared__ float b3s;
    __shared__ int   eids[128];
    int tid = threadIdx.x;

    for (int i = tid; i < 64 * 32; i += 128) w2s[i] = Wp2[i];
    if (tid < 32)       b2s[tid]      = bp2[tid];
    else if (tid < 64)  w3s[tid - 32] = Wp3[tid - 32];
    if (tid == 64) b3s = bp3[0];

    // Phase A: one thread per CSR slot; z1 = relu(a_pre[s] + (c_pre[d]+bp1))
    int slot = blockIdx.x * 128 + tid;   // NE % 128 == 0
    int s = g_csr_src[slot], d = g_csr_dst[slot];
    eids[tid] = g_csr_eid[slot];
    const float* ps = &g_pre[(size_t)s * 128];
    const float* pd = &g_pre[(size_t)d * 128 + 64];
#pragma unroll
    for (int j = 0; j < 64; j += 4) {
        float4 a = *(const float4*)&ps[j];
        float4 c = *(const float4*)&pd[j];
        z1s[(j + 0) * 132 + tid] = fmaxf(a.x + c.x, 0.f);
        z1s[(j + 1) * 132 + tid] = fmaxf(a.y + c.y, 0.f);
        z1s[(j + 2) * 132 + tid] = fmaxf(a.z + c.z, 0.f);
        z1s[(j + 3) * 132 + tid] = fmaxf(a.w + c.w, 0.f);
    }
    __syncthreads();

    // Phase B: 8 edges x 4 cols per thread
    int tx = tid & 7;
    int ey = tid >> 3;
    float acc[8][4];
#pragma unroll
    for (int r = 0; r < 8; r++)
#pragma unroll
        for (int c = 0; c < 4; c++) acc[r][c] = 0.f;

#pragma unroll 4
    for (int k = 0; k < 64; k++) {
        float4 w  = *(const float4*)&w2s[k * 32 + tx * 4];
        float4 z0 = *(const float4*)&z1s[k * 132 + ey * 8];
        float4 z1 = *(const float4*)&z1s[k * 132 + ey * 8 + 4];
        float ww[4] = { w.x, w.y, w.z, w.w };
        float zz[8] = { z0.x, z0.y, z0.z, z0.w, z1.x, z1.y, z1.z, z1.w };
#pragma unroll
        for (int r = 0; r < 8; r++)
#pragma unroll
            for (int c = 0; c < 4; c++) acc[r][c] = fmaf(zz[r], ww[c], acc[r][c]);
    }

    // Phase C
    float4 w3  = *(const float4*)&w3s[tx * 4];
    float4 bb2 = *(const float4*)&b2s[tx * 4];
    float pscore[8];
#pragma unroll
    for (int r = 0; r < 8; r++) {
        float q0 = fmaxf(acc[r][0] + bb2.x, 0.f);
        float q1 = fmaxf(acc[r][1] + bb2.y, 0.f);
        float q2 = fmaxf(acc[r][2] + bb2.z, 0.f);
        float q3 = fmaxf(acc[r][3] + bb2.w, 0.f);
        pscore[r] = q0 * w3.x + q1 * w3.y + q2 * w3.z + q3 * w3.w;
    }
#pragma unroll
    for (int off = 4; off >= 1; off >>= 1)
#pragma unroll
        for (int r = 0; r < 8; r++)
            pscore[r] += __shfl_down_sync(0xffffffffu, pscore[r], off, 8);

    if (tx == 0) {
#pragma unroll
        for (int r = 0; r < 8; r++) {
            float sc = pscore[r] + b3s;
            out[eids[ey * 8 + r]] = 1.f / (1.f + expf(-sc));
        }
    }
}

// ---------------- launch ----------------
extern "C" void kernel_launch(void* const* d_in, const int* in_sizes, int n_in,
                              void* d_out, int out_size) {
    const float* x   = (const float*)d_in[0];
    const void*  src = d_in[1];
    const void*  dst = d_in[2];
    const float* W1  = (const float*)d_in[3];
    const float* b1  = (const float*)d_in[4];
    const float* W2  = (const float*)d_in[5];
    const float* b2  = (const float*)d_in[6];
    const float* Wp1 = (const float*)d_in[7];
    const float* bp1 = (const float*)d_in[8];
    const float* Wp2 = (const float*)d_in[9];
    const float* bp2 = (const float*)d_in[10];
    const float* Wp3 = (const float*)d_in[11];
    const float* bp3 = (const float*)d_in[12];
    float* out = (float*)d_out;

    __half *h1tmp, *h2tmp;
    float *agg1, *agg2, *pre;
    cudaGetSymbolAddress((void**)&h1tmp, g_h1tmp);
    cudaGetSymbolAddress((void**)&agg1,  g_agg1);
    cudaGetSymbolAddress((void**)&h2tmp, g_h2tmp);
    cudaGetSymbolAddress((void**)&agg2,  g_agg2);
    cudaGetSymbolAddress((void**)&pre,   g_pre);

    // side stream + events, created on the first (non-captured) call
    static cudaStream_t s1 = nullptr;
    static cudaEvent_t evA = nullptr, evB = nullptr;
    if (s1 == nullptr) {
        cudaStreamCreateWithFlags(&s1, cudaStreamNonBlocking);
        cudaEventCreateWithFlags(&evA, cudaEventDisableTiming);
        cudaEventCreateWithFlags(&evB, cudaEventDisableTiming);
    }

    zero_k<<<512, 256>>>(src);
    convert_deg_k<<<NE / 256, 256>>>(src, dst);

    // fork: CSR build (scan + bin) on s1, overlapped with gemm1
    cudaEventRecord(evA, 0);
    cudaStreamWaitEvent(s1, evA, 0);
    scanA_k<<<NBLK_SCAN, 1024, 0, s1>>>();
    scanB_k<<<1, 128, 0, s1>>>();
    scanC_k<<<(NN + 255) / 256, 256, 0, s1>>>();
    bin_k<<<NE / 256, 256, 0, s1>>>();
    cudaEventRecord(evB, s1);

    gemm_k<128, 128, 64, 32, 1, 0><<<(NN + 63) / 64, 256>>>(x, W1, b1, nullptr, h1tmp);

    // join before aggregation needs the CSR
    cudaStreamWaitEvent(0, evB, 0);
    agg_k<128><<<(NN * 32 + 255) / 256, 256>>>(h1tmp, agg1);

    gemm_k<128, 64, 128, 16, 2, 0><<<(NN + 127) / 128, 256>>>(agg1, W2, b1, nullptr, h2tmp);
    agg_k<64><<<(NN * 32 + 255) / 256, 256>>>(h2tmp, agg2);

    // pre = (agg2*rs_in + b2) @ [Wp1_top | Wp1_bot]; +bp1 folded into cols 64..127
    gemm_k<64, 128, 64, 32, 3, 1><<<(NN + 63) / 64, 256>>>(agg2, Wp1, b2, bp1, pre);

    // per-edge MLP + sigmoid, CSR(dst) order, scatter by eid
    edge_mlp_k<<<NE / 128, 128>>>(Wp2, bp2, Wp3, bp3, out);
}

// round 14
// speedup vs baseline: 1.5591x; 1.2933x over previous
#include <cuda_runtime.h>
#include <cuda_fp16.h>
#include <math.h>

#define NN 100000
#define NE 1600000
#define NBLK_SCAN 98   // ceil(NN/1024)

// ---------------- device scratch (no allocations allowed) ----------------
__device__ int    g_is64;
__device__ int    g_src32[NE];
__device__ int    g_dst32[NE];
__device__ int    g_deg_out[NN];
__device__ int    g_deg_in[NN];
__device__ int    g_ptr[NN];        // CSR row offsets (by dst)
__device__ int    g_fill[NN];       // binning cursors
__device__ int    g_bsum[128];      // scan block sums
__device__ int    g_csr_src[NE];    // src node per CSR slot
__device__ int    g_csr_dst[NE];    // dst node per CSR slot
__device__ int    g_csr_eid[NE];    // original edge id per CSR slot
__device__ __half g_h1tmp[(size_t)NN * 128];   // fp16: halves agg1 gather traffic
__device__ float  g_agg1 [(size_t)NN * 128];
__device__ __half g_h2tmp[(size_t)NN * 64];    // fp16: halves agg2 gather traffic
__device__ float  g_agg2 [(size_t)NN * 64];
__device__ __half g_pre  [(size_t)NN * 128];   // fp16: [:,0:64]=a_pre(src), [:,64:128]=c_pre(dst)+bp1

__device__ __forceinline__ float rs_of(int deg) {
    return rsqrtf(fmaxf((float)deg, 1.f));
}

// ---------------- zero degree counters + index-width detect ----------------
__global__ void zero_k(const void* src) {
    int tid = blockIdx.x * blockDim.x + threadIdx.x;
    int stride = gridDim.x * blockDim.x;
    for (int i = tid; i < NN; i += stride) { g_deg_out[i] = 0; g_deg_in[i] = 0; }
    if (blockIdx.x == 0 && threadIdx.x < 32) {
        const long long* p = (const long long*)src;
        bool ok = true;
        for (int i = threadIdx.x; i < 256; i += 32) {
            long long v = p[i];
            if (v < 0 || v >= NN) ok = false;
        }
        unsigned m = __ballot_sync(0xffffffffu, ok);
        if (threadIdx.x == 0) g_is64 = (m == 0xffffffffu) ? 1 : 0;
    }
}

// ---------------- normalize indices to int32 + degree histogram ----------------
__global__ void convert_deg_k(const void* srcp, const void* dstp) {
    int e = blockIdx.x * blockDim.x + threadIdx.x;
    if (e >= NE) return;
    int s, d;
    if (g_is64) {
        s = (int)((const long long*)srcp)[e];
        d = (int)((const long long*)dstp)[e];
    } else {
        s = ((const int*)srcp)[e];
        d = ((const int*)dstp)[e];
    }
    g_src32[e] = s;
    g_dst32[e] = d;
    atomicAdd(&g_deg_out[s], 1);
    atomicAdd(&g_deg_in[d], 1);
}

// ---------------- exclusive scan of deg_in ----------------
__global__ __launch_bounds__(1024) void scanA_k() {
    int n = blockIdx.x * 1024 + threadIdx.x;
    int v = (n < NN) ? g_deg_in[n] : 0;
    int lane = threadIdx.x & 31, wid = threadIdx.x >> 5;
    int x = v;
#pragma unroll
    for (int o = 1; o < 32; o <<= 1) {
        int y = __shfl_up_sync(0xffffffffu, x, o);
        if (lane >= o) x += y;
    }
    __shared__ int wsum[32];
    if (lane == 31) wsum[wid] = x;
    __syncthreads();
    if (wid == 0) {
        int t = wsum[lane];
#pragma unroll
        for (int o = 1; o < 32; o <<= 1) {
            int y = __shfl_up_sync(0xffffffffu, t, o);
            if (lane >= o) t += y;
        }
        wsum[lane] = t;
    }
    __syncthreads();
    int base = (wid > 0) ? wsum[wid - 1] : 0;
    int excl = base + x - v;
    if (n < NN) g_ptr[n] = excl;
    if (threadIdx.x == 1023) g_bsum[blockIdx.x] = excl + v;
}

__global__ void scanB_k() {
    int i = threadIdx.x, lane = i & 31, w = i >> 5;
    int v = (i < NBLK_SCAN) ? g_bsum[i] : 0;
    int x = v;
#pragma unroll
    for (int o = 1; o < 32; o <<= 1) {
        int y = __shfl_up_sync(0xffffffffu, x, o);
        if (lane >= o) x += y;
    }
    __shared__ int ws[4];
    if (lane == 31) ws[w] = x;
    __syncthreads();
    int off = 0;
    for (int k = 0; k < w; k++) off += ws[k];
    if (i < NBLK_SCAN) g_bsum[i] = off + x - v;
}

// fixup + init fill cursors
__global__ void scanC_k() {
    int n = blockIdx.x * 256 + threadIdx.x;
    if (n >= NN) return;
    int p = g_ptr[n] + g_bsum[n >> 10];
    g_ptr[n] = p;
    g_fill[n] = p;
}

// ---------------- bin edges by dst (records src, dst, original eid) ----------------
__global__ void bin_k() {
    int e = blockIdx.x * 256 + threadIdx.x;
    if (e >= NE) return;
    int d = g_dst32[e];
    int slot = atomicAdd(&g_fill[d], 1);
    g_csr_src[slot] = g_src32[e];
    g_csr_dst[slot] = d;
    g_csr_eid[slot] = e;
}

// ---------------- CSR aggregation (fp16 input rows, fp32 accum) ----------------
template<int DIM>
__global__ __launch_bounds__(256) void agg_k(const __half* __restrict__ H,
                                             float* __restrict__ AG) {
    int warp = (blockIdx.x * 256 + threadIdx.x) >> 5;
    if (warp >= NN) return;
    int lane = threadIdx.x & 31;
    int ptr = g_ptr[warp];
    int deg = g_deg_in[warp];
    if (DIM == 128) {
        float4 acc = make_float4(0.f, 0.f, 0.f, 0.f);
        for (int base = 0; base < deg; base += 32) {
            int cnt = min(32, deg - base);
            int idx = (base + lane < deg) ? g_csr_src[ptr + base + lane] : 0;
            for (int j = 0; j < cnt; j++) {
                int s = __shfl_sync(0xffffffffu, idx, j);
                uint2 u = *(const uint2*)&H[(size_t)s * 128 + lane * 4];
                float2 f0 = __half22float2(*(__half2*)&u.x);
                float2 f1 = __half22float2(*(__half2*)&u.y);
                acc.x += f0.x; acc.y += f0.y; acc.z += f1.x; acc.w += f1.y;
            }
        }
        *(float4*)&AG[(size_t)warp * 128 + lane * 4] = acc;
    } else {
        float2 acc = make_float2(0.f, 0.f);
        for (int base = 0; base < deg; base += 32) {
            int cnt = min(32, deg - base);
            int idx = (base + lane < deg) ? g_csr_src[ptr + base + lane] : 0;
            for (int j = 0; j < cnt; j++) {
                int s = __shfl_sync(0xffffffffu, idx, j);
                unsigned u = *(const unsigned*)&H[(size_t)s * 64 + lane * 2];
                float2 f0 = __half22float2(*(__half2*)&u);
                acc.x += f0.x; acc.y += f0.y;
            }
        }
        *(float2*)&AG[(size_t)warp * 64 + lane * 2] = acc;
    }
}

// ---------------- node GEMM, k-major activation tile, scalar FFMA ----------------
// PRE: 1 A*rs(deg_out) | 2 relu(A*rs(deg_in)+bias)*rs(deg_out) | 3 A*rs(deg_in)+bias
// WMAP: 0 W is [K x NOUT] row-major | 1 split map of Wp1[128x64]; epilogue adds
//       ebias[j-64] to columns j>=64. OT: float or __half output.
template<int K, int NOUT, int NODES, int TX, int PRE, int WMAP, typename OT>
__global__ __launch_bounds__(256) void gemm_k(
    const float* __restrict__ A, const float* __restrict__ W,
    const float* __restrict__ bias, const float* __restrict__ ebias,
    OT* __restrict__ C)
{
    constexpr int NPT = NOUT / TX;      // 4
    constexpr int TY  = 256 / TX;
    constexpr int RPT = NODES / TY;     // 8
    constexpr int KC  = 32;
    constexpr int KG  = KC / 4;
    constexpr int XSTR = NODES + 4;
    static_assert(NPT == 4 && RPT == 8, "blocking assumption");
    __shared__ __align__(16) float Ws[KC * NOUT];
    __shared__ __align__(16) float Xs[KC * XSTR];
    int tid = threadIdx.x;
    int tx = tid % TX, ty = tid / TX;
    int nb = blockIdx.x * NODES;

    float acc[RPT][NPT];
#pragma unroll
    for (int r = 0; r < RPT; r++)
#pragma unroll
        for (int c = 0; c < NPT; c++) acc[r][c] = 0.f;

    for (int p = 0; p < K / KC; p++) {
        for (int idx = tid * 4; idx < KC * NOUT; idx += 1024) {
            int kk = idx / NOUT, j = idx % NOUT;
            int k = p * KC + kk;
            float4 w;
            if (WMAP == 0) {
                w = *(const float4*)&W[(size_t)k * NOUT + j];
            } else {
                if (j < 64) w = *(const float4*)&W[k * 64 + j];
                else        w = *(const float4*)&W[(64 + k) * 64 + (j - 64)];
            }
            *(float4*)&Ws[kk * NOUT + j] = w;
        }
        for (int idx = tid; idx < NODES * KG; idx += 256) {
            int nl = idx / KG, kg = idx % KG;
            int n = nb + nl;
            int k = p * KC + kg * 4;
            float v0 = 0.f, v1 = 0.f, v2 = 0.f, v3 = 0.f;
            if (n < NN) {
                float4 t = *(const float4*)&A[(size_t)n * K + k];
                if (PRE == 1) {
                    float ro = rs_of(g_deg_out[n]);
                    v0 = t.x * ro; v1 = t.y * ro; v2 = t.z * ro; v3 = t.w * ro;
                } else if (PRE == 2) {
                    float ri = rs_of(g_deg_in[n]), ro = rs_of(g_deg_out[n]);
                    float4 bb = *(const float4*)&bias[k];
                    v0 = fmaxf(fmaf(t.x, ri, bb.x), 0.f) * ro;
                    v1 = fmaxf(fmaf(t.y, ri, bb.y), 0.f) * ro;
                    v2 = fmaxf(fmaf(t.z, ri, bb.z), 0.f) * ro;
                    v3 = fmaxf(fmaf(t.w, ri, bb.w), 0.f) * ro;
                } else {
                    float ri = rs_of(g_deg_in[n]);
                    float4 bb = *(const float4*)&bias[k];
                    v0 = fmaf(t.x, ri, bb.x);
                    v1 = fmaf(t.y, ri, bb.y);
                    v2 = fmaf(t.z, ri, bb.z);
                    v3 = fmaf(t.w, ri, bb.w);
                }
            }
            int kb = kg * 4;
            Xs[(kb + 0) * XSTR + nl] = v0;
            Xs[(kb + 1) * XSTR + nl] = v1;
            Xs[(kb + 2) * XSTR + nl] = v2;
            Xs[(kb + 3) * XSTR + nl] = v3;
        }
        __syncthreads();
#pragma unroll
        for (int kk = 0; kk < KC; kk++) {
            float4 w = *(const float4*)&Ws[kk * NOUT + tx * NPT];
            const float* xp = &Xs[kk * XSTR + ty * RPT];
            float4 x0 = *(const float4*)xp;
            float4 x1 = *(const float4*)(xp + 4);
            float wv[4] = { w.x, w.y, w.z, w.w };
            float xv[8] = { x0.x, x0.y, x0.z, x0.w, x1.x, x1.y, x1.z, x1.w };
#pragma unroll
            for (int r = 0; r < RPT; r++)
#pragma unroll
                for (int c = 0; c < NPT; c++) acc[r][c] = fmaf(xv[r], wv[c], acc[r][c]);
        }
        __syncthreads();
    }
    float4 eb = make_float4(0.f, 0.f, 0.f, 0.f);
    if (WMAP == 1 && tx >= 16) eb = *(const float4*)&ebias[tx * 4 - 64];
#pragma unroll
    for (int r = 0; r < RPT; r++) {
        int n = nb + ty * RPT + r;
        if (n < NN) {
            float o0 = acc[r][0] + eb.x, o1 = acc[r][1] + eb.y;
            float o2 = acc[r][2] + eb.z, o3 = acc[r][3] + eb.w;
            if (sizeof(OT) == 2) {
                __half2 p0 = __floats2half2_rn(o0, o1);
                __half2 p1 = __floats2half2_rn(o2, o3);
                unsigned u0 = *reinterpret_cast<unsigned*>(&p0);
                unsigned u1 = *reinterpret_cast<unsigned*>(&p1);
                *(uint2*)&C[(size_t)n * NOUT + tx * NPT] = make_uint2(u0, u1);
            } else {
                *(float4*)&C[(size_t)n * NOUT + tx * NPT] = make_float4(o0, o1, o2, o3);
            }
        }
    }
}

// ---------------- per-edge MLP, CSR(dst) order, HFMA2 phase B ----------------
// 256 threads / 256 edges per block. z1 stored as half2 over edge PAIRS, k-major.
#define PSTR 132   // pair stride (128 pairs + pad)
__global__ __launch_bounds__(256) void edge_mlp_k(
    const float* __restrict__ Wp2, const float* __restrict__ bp2,
    const float* __restrict__ Wp3, const float* __restrict__ bp3,
    float* __restrict__ out)
{
    __shared__ __align__(16) __half2 z1s[64 * PSTR];   // [k][pair]
    __shared__ __align__(16) __half2 w2s[64 * 32];     // [k][n] broadcast (w,w)
    __shared__ float b2s[32];
    __shared__ float w3s[32];
    __shared__ float b3s;
    __shared__ int   eids[256];
    int tid = threadIdx.x;

    for (int i = tid; i < 64 * 32; i += 256) w2s[i] = __float2half2_rn(Wp2[i]);
    if (tid < 32)       b2s[tid]      = bp2[tid];
    else if (tid < 64)  w3s[tid - 32] = Wp3[tid - 32];
    if (tid == 64) b3s = bp3[0];

    // Phase A: one thread per CSR slot; z1 = relu(a_pre[s] + c_pre[d]) in half2
    int slot = blockIdx.x * 256 + tid;   // NE % 256 == 0
    int s = g_csr_src[slot], d = g_csr_dst[slot];
    eids[tid] = g_csr_eid[slot];
    const uint4* ps = (const uint4*)&g_pre[(size_t)s * 128];
    const uint4* pd = (const uint4*)&g_pre[(size_t)d * 128 + 64];
    int pr = tid >> 1, hh = tid & 1;
    __half* z1h = (__half*)z1s;
    const __half2 hz = __float2half2_rn(0.f);
#pragma unroll
    for (int g = 0; g < 8; g++) {
        uint4 ua = ps[g];            // 8 halfs: k = g*8 .. g*8+7 (src part)
        uint4 uc = pd[g];            // dst part (+bp1 folded)
        __half2 zz[4];
        zz[0] = __hmax2(__hadd2(*(__half2*)&ua.x, *(__half2*)&uc.x), hz);
        zz[1] = __hmax2(__hadd2(*(__half2*)&ua.y, *(__half2*)&uc.y), hz);
        zz[2] = __hmax2(__hadd2(*(__half2*)&ua.z, *(__half2*)&uc.z), hz);
        zz[3] = __hmax2(__hadd2(*(__half2*)&ua.w, *(__half2*)&uc.w), hz);
#pragma unroll
        for (int q = 0; q < 4; q++) {
            int k0 = g * 8 + q * 2;
            z1h[(k0 * PSTR + pr) * 2 + hh]       = __low2half(zz[q]);
            z1h[((k0 + 1) * PSTR + pr) * 2 + hh] = __high2half(zz[q]);
        }
    }
    __syncthreads();

    // Phase B: HFMA2 over edge pairs; 4 pairs (8 edges) x 4 cols per thread.
    // fp16 accumulation in 16-k chunks, promoted to fp32 between chunks.
    int tx = tid & 7;    // col group (4 cols)
    int ey = tid >> 3;   // pair group (4 pairs): 32 groups * 4 = 128 pairs
    float accf[8][4];
#pragma unroll
    for (int r = 0; r < 8; r++)
#pragma unroll
        for (int c = 0; c < 4; c++) accf[r][c] = 0.f;

#pragma unroll
    for (int kc = 0; kc < 4; kc++) {
        __half2 acch[4][4];
#pragma unroll
        for (int p = 0; p < 4; p++)
#pragma unroll
            for (int c = 0; c < 4; c++) acch[p][c] = hz;
#pragma unroll
        for (int kk = 0; kk < 16; kk++) {
            int k = kc * 16 + kk;
            uint4 uw = *(const uint4*)&w2s[k * 32 + tx * 4];
            uint4 uz = *(const uint4*)&z1s[k * PSTR + ey * 4];
            __half2 wv[4] = { *(__half2*)&uw.x, *(__half2*)&uw.y,
                              *(__half2*)&uw.z, *(__half2*)&uw.w };
            __half2 zp[4] = { *(__half2*)&uz.x, *(__half2*)&uz.y,
                              *(__half2*)&uz.z, *(__half2*)&uz.w };
#pragma unroll
            for (int p = 0; p < 4; p++)
#pragma unroll
                for (int c = 0; c < 4; c++)
                    acch[p][c] = __hfma2(zp[p], wv[c], acch[p][c]);
        }
#pragma unroll
        for (int p = 0; p < 4; p++)
#pragma unroll
            for (int c = 0; c < 4; c++) {
                float2 f = __half22float2(acch[p][c]);
                accf[2 * p][c]     += f.x;
                accf[2 * p + 1][c] += f.y;
            }
    }

    // Phase C: relu + bias, dot with Wp3, reduce across the 8 col-groups
    float4 w3  = *(const float4*)&w3s[tx * 4];
    float4 bb2 = *(const float4*)&b2s[tx * 4];
    float pscore[8];
#pragma unroll
    for (int r = 0; r < 8; r++) {
        float q0 = fmaxf(accf[r][0] + bb2.x, 0.f);
        float q1 = fmaxf(accf[r][1] + bb2.y, 0.f);
        float q2 = fmaxf(accf[r][2] + bb2.z, 0.f);
        float q3 = fmaxf(accf[r][3] + bb2.w, 0.f);
        pscore[r] = q0 * w3.x + q1 * w3.y + q2 * w3.z + q3 * w3.w;
    }
#pragma unroll
    for (int off = 4; off >= 1; off >>= 1)
#pragma unroll
        for (int r = 0; r < 8; r++)
            pscore[r] += __shfl_down_sync(0xffffffffu, pscore[r], off, 8);

    if (tx == 0) {
#pragma unroll
        for (int r = 0; r < 8; r++) {
            float sc = pscore[r] + b3s;
            out[eids[ey * 8 + r]] = 1.f / (1.f + expf(-sc));
        }
    }
}

// ---------------- launch ----------------
extern "C" void kernel_launch(void* const* d_in, const int* in_sizes, int n_in,
                              void* d_out, int out_size) {
    const float* x   = (const float*)d_in[0];
    const void*  src = d_in[1];
    const void*  dst = d_in[2];
    const float* W1  = (const float*)d_in[3];
    const float* b1  = (const float*)d_in[4];
    const float* W2  = (const float*)d_in[5];
    const float* b2  = (const float*)d_in[6];
    const float* Wp1 = (const float*)d_in[7];
    const float* bp1 = (const float*)d_in[8];
    const float* Wp2 = (const float*)d_in[9];
    const float* bp2 = (const float*)d_in[10];
    const float* Wp3 = (const float*)d_in[11];
    const float* bp3 = (const float*)d_in[12];
    float* out = (float*)d_out;

    __half *h1tmp, *h2tmp, *pre;
    float *agg1, *agg2;
    cudaGetSymbolAddress((void**)&h1tmp, g_h1tmp);
    cudaGetSymbolAddress((void**)&agg1,  g_agg1);
    cudaGetSymbolAddress((void**)&h2tmp, g_h2tmp);
    cudaGetSymbolAddress((void**)&agg2,  g_agg2);
    cudaGetSymbolAddress((void**)&pre,   g_pre);

    // side stream + events, created on the first (non-captured) call
    static cudaStream_t s1 = nullptr;
    static cudaEvent_t evA = nullptr, evB = nullptr;
    if (s1 == nullptr) {
        cudaStreamCreateWithFlags(&s1, cudaStreamNonBlocking);
        cudaEventCreateWithFlags(&evA, cudaEventDisableTiming);
        cudaEventCreateWithFlags(&evB, cudaEventDisableTiming);
    }

    zero_k<<<512, 256>>>(src);
    convert_deg_k<<<NE / 256, 256>>>(src, dst);

    // fork: CSR build (scan + bin) on s1, overlapped with gemm1
    cudaEventRecord(evA, 0);
    cudaStreamWaitEvent(s1, evA, 0);
    scanA_k<<<NBLK_SCAN, 1024, 0, s1>>>();
    scanB_k<<<1, 128, 0, s1>>>();
    scanC_k<<<(NN + 255) / 256, 256, 0, s1>>>();
    bin_k<<<NE / 256, 256, 0, s1>>>();
    cudaEventRecord(evB, s1);

    gemm_k<128, 128, 64, 32, 1, 0><<<(NN + 63) / 64, 256>>>(x, W1, b1, nullptr, h1tmp);

    // join before aggregation needs the CSR
    cudaStreamWaitEvent(0, evB, 0);
    agg_k<128><<<(NN * 32 + 255) / 256, 256>>>(h1tmp, agg1);

    gemm_k<128, 64, 128, 16, 2, 0><<<(NN + 127) / 128, 256>>>(agg1, W2, b1, nullptr, h2tmp);
    agg_k<64><<<(NN * 32 + 255) / 256, 256>>>(h2tmp, agg2);

    // pre = (agg2*rs_in + b2) @ [Wp1_top | Wp1_bot]; +bp1 folded into cols 64..127
    gemm_k<64, 128, 64, 32, 3, 1><<<(NN + 63) / 64, 256>>>(agg2, Wp1, b2, bp1, pre);

    // per-edge MLP + sigmoid, CSR(dst) order, HFMA2 phase B
    edge_mlp_k<<<NE / 256, 256>>>(Wp2, bp2, Wp3, bp3, out);
}

// round 17
// speedup vs baseline: 1.6528x; 1.0601x over previous
#include <cuda_runtime.h>
#include <cuda_fp16.h>
#include <math.h>

#define NN 100000
#define NE 1600000
#define NBLK_SCAN 98   // ceil(NN/1024)

// ---------------- device scratch (no allocations allowed) ----------------
__device__ int    g_is64;
__device__ int    g_src32[NE];
__device__ int    g_dst32[NE];
__device__ int    g_deg_out[NN];
__device__ int    g_deg_in[NN];
__device__ int    g_ptr[NN];        // CSR row offsets (by dst)
__device__ int    g_fill[NN];       // binning cursors
__device__ int    g_bsum[128];      // scan block sums
__device__ int    g_csr_src[NE];    // src node per CSR slot
__device__ int    g_csr_dst[NE];    // dst node per CSR slot
__device__ int    g_csr_eid[NE];    // original edge id per CSR slot
__device__ __half g_h1tmp[(size_t)NN * 128];
__device__ float  g_agg1 [(size_t)NN * 128];
__device__ __half g_h2tmp[(size_t)NN * 64];
__device__ float  g_agg2 [(size_t)NN * 64];
__device__ __half g_pre  [(size_t)NN * 128];   // [:,0:64]=a_pre(src), [:,64:128]=c_pre(dst)+bp1

__device__ __forceinline__ float rs_of(int deg) {
    return rsqrtf(fmaxf((float)deg, 1.f));
}

// ---------------- zero degree counters + index-width detect ----------------
__global__ void zero_k(const void* src) {
    int tid = blockIdx.x * blockDim.x + threadIdx.x;
    int stride = gridDim.x * blockDim.x;
    for (int i = tid; i < NN; i += stride) { g_deg_out[i] = 0; g_deg_in[i] = 0; }
    if (blockIdx.x == 0 && threadIdx.x < 32) {
        const long long* p = (const long long*)src;
        bool ok = true;
        for (int i = threadIdx.x; i < 256; i += 32) {
            long long v = p[i];
            if (v < 0 || v >= NN) ok = false;
        }
        unsigned m = __ballot_sync(0xffffffffu, ok);
        if (threadIdx.x == 0) g_is64 = (m == 0xffffffffu) ? 1 : 0;
    }
}

// ---------------- normalize indices to int32 + degree histogram ----------------
__global__ void convert_deg_k(const void* srcp, const void* dstp) {
    int e = blockIdx.x * blockDim.x + threadIdx.x;
    if (e >= NE) return;
    int s, d;
    if (g_is64) {
        s = (int)((const long long*)srcp)[e];
        d = (int)((const long long*)dstp)[e];
    } else {
        s = ((const int*)srcp)[e];
        d = ((const int*)dstp)[e];
    }
    g_src32[e] = s;
    g_dst32[e] = d;
    atomicAdd(&g_deg_out[s], 1);
    atomicAdd(&g_deg_in[d], 1);
}

// ---------------- exclusive scan of deg_in ----------------
__global__ __launch_bounds__(1024) void scanA_k() {
    int n = blockIdx.x * 1024 + threadIdx.x;
    int v = (n < NN) ? g_deg_in[n] : 0;
    int lane = threadIdx.x & 31, wid = threadIdx.x >> 5;
    int x = v;
#pragma unroll
    for (int o = 1; o < 32; o <<= 1) {
        int y = __shfl_up_sync(0xffffffffu, x, o);
        if (lane >= o) x += y;
    }
    __shared__ int wsum[32];
    if (lane == 31) wsum[wid] = x;
    __syncthreads();
    if (wid == 0) {
        int t = wsum[lane];
#pragma unroll
        for (int o = 1; o < 32; o <<= 1) {
            int y = __shfl_up_sync(0xffffffffu, t, o);
            if (lane >= o) t += y;
        }
        wsum[lane] = t;
    }
    __syncthreads();
    int base = (wid > 0) ? wsum[wid - 1] : 0;
    int excl = base + x - v;
    if (n < NN) g_ptr[n] = excl;
    if (threadIdx.x == 1023) g_bsum[blockIdx.x] = excl + v;
}

__global__ void scanB_k() {
    int i = threadIdx.x, lane = i & 31, w = i >> 5;
    int v = (i < NBLK_SCAN) ? g_bsum[i] : 0;
    int x = v;
#pragma unroll
    for (int o = 1; o < 32; o <<= 1) {
        int y = __shfl_up_sync(0xffffffffu, x, o);
        if (lane >= o) x += y;
    }
    __shared__ int ws[4];
    if (lane == 31) ws[w] = x;
    __syncthreads();
    int off = 0;
    for (int k = 0; k < w; k++) off += ws[k];
    if (i < NBLK_SCAN) g_bsum[i] = off + x - v;
}

// fixup + init fill cursors
__global__ void scanC_k() {
    int n = blockIdx.x * 256 + threadIdx.x;
    if (n >= NN) return;
    int p = g_ptr[n] + g_bsum[n >> 10];
    g_ptr[n] = p;
    g_fill[n] = p;
}

// ---------------- bin edges by dst (records src, dst, original eid) ----------------
__global__ void bin_k() {
    int e = blockIdx.x * 256 + threadIdx.x;
    if (e >= NE) return;
    int d = g_dst32[e];
    int slot = atomicAdd(&g_fill[d], 1);
    g_csr_src[slot] = g_src32[e];
    g_csr_dst[slot] = d;
    g_csr_eid[slot] = e;
}

// ---------------- CSR aggregation (fp16 input rows, fp32 accum) ----------------
template<int DIM>
__global__ __launch_bounds__(256) void agg_k(const __half* __restrict__ H,
                                             float* __restrict__ AG) {
    int warp = (blockIdx.x * 256 + threadIdx.x) >> 5;
    if (warp >= NN) return;
    int lane = threadIdx.x & 31;
    int ptr = g_ptr[warp];
    int deg = g_deg_in[warp];
    if (DIM == 128) {
        float4 acc = make_float4(0.f, 0.f, 0.f, 0.f);
        for (int base = 0; base < deg; base += 32) {
            int cnt = min(32, deg - base);
            int idx = (base + lane < deg) ? g_csr_src[ptr + base + lane] : 0;
            for (int j = 0; j < cnt; j++) {
                int s = __shfl_sync(0xffffffffu, idx, j);
                uint2 u = *(const uint2*)&H[(size_t)s * 128 + lane * 4];
                float2 f0 = __half22float2(*(__half2*)&u.x);
                float2 f1 = __half22float2(*(__half2*)&u.y);
                acc.x += f0.x; acc.y += f0.y; acc.z += f1.x; acc.w += f1.y;
            }
        }
        *(float4*)&AG[(size_t)warp * 128 + lane * 4] = acc;
    } else {
        float2 acc = make_float2(0.f, 0.f);
        for (int base = 0; base < deg; base += 32) {
            int cnt = min(32, deg - base);
            int idx = (base + lane < deg) ? g_csr_src[ptr + base + lane] : 0;
            for (int j = 0; j < cnt; j++) {
                int s = __shfl_sync(0xffffffffu, idx, j);
                unsigned u = *(const unsigned*)&H[(size_t)s * 64 + lane * 2];
                float2 f0 = __half22float2(*(__half2*)&u);
                acc.x += f0.x; acc.y += f0.y;
            }
        }
        *(float2*)&AG[(size_t)warp * 64 + lane * 2] = acc;
    }
}

// ---------------- node GEMM, half2 pairs k-major + HFMA2 ----------------
// PRE: 1 A*rs(deg_out) | 2 relu(A*rs(deg_in)+bias)*rs(deg_out) | 3 A*rs(deg_in)+bias
// WMAP: 0 W [K x NOUT] row-major | 1 split map of Wp1[128x64]; epilogue adds
//       ebias[j-64] to cols j>=64. OT: float or __half output.
template<int K, int NOUT, int NODES, int TX, int PRE, int WMAP, typename OT>
__global__ __launch_bounds__(256) void gemm_k(
    const float* __restrict__ A, const float* __restrict__ W,
    const float* __restrict__ bias, const float* __restrict__ ebias,
    OT* __restrict__ C)
{
    constexpr int NPT = NOUT / TX;      // 4
    constexpr int TY  = 256 / TX;
    constexpr int RPT = NODES / TY;     // 8 nodes = 4 pairs per thread
    constexpr int KC  = 32;
    constexpr int KG  = KC / 4;
    constexpr int NPAIR = NODES / 2;
    constexpr int PSTRG = NPAIR + 4;    // pad; multiple of 4 half2 -> 16B-aligned uint4 reads
    static_assert(NPT == 4 && RPT == 8, "blocking assumption");
    static_assert(PSTRG % 4 == 0, "uint4 alignment");
    __shared__ __align__(16) __half2 Ws2[KC * NOUT];   // broadcast (w,w)
    __shared__ __align__(16) __half2 Xs2[KC * PSTRG];  // [kk][pair]
    int tid = threadIdx.x;
    int tx = tid % TX, ty = tid / TX;
    int nb = blockIdx.x * NODES;
    const __half2 hz = __float2half2_rn(0.f);

    float accf[RPT][NPT];
#pragma unroll
    for (int r = 0; r < RPT; r++)
#pragma unroll
        for (int c = 0; c < NPT; c++) accf[r][c] = 0.f;

    for (int p = 0; p < K / KC; p++) {
        // stage weights as broadcast half2
        for (int idx = tid * 4; idx < KC * NOUT; idx += 1024) {
            int kk = idx / NOUT, j = idx % NOUT;
            int k = p * KC + kk;
            float4 w;
            if (WMAP == 0) {
                w = *(const float4*)&W[(size_t)k * NOUT + j];
            } else {
                if (j < 64) w = *(const float4*)&W[k * 64 + j];
                else        w = *(const float4*)&W[(64 + k) * 64 + (j - 64)];
            }
            Ws2[kk * NOUT + j + 0] = __float2half2_rn(w.x);
            Ws2[kk * NOUT + j + 1] = __float2half2_rn(w.y);
            Ws2[kk * NOUT + j + 2] = __float2half2_rn(w.z);
            Ws2[kk * NOUT + j + 3] = __float2half2_rn(w.w);
        }
        // stage activations: fp32 preprocess, store half into pair layout
        __half* xh = (__half*)Xs2;
        for (int idx = tid; idx < NODES * KG; idx += 256) {
            int nl = idx / KG, kg = idx % KG;
            int n = nb + nl;
            int k = p * KC + kg * 4;
            float v0 = 0.f, v1 = 0.f, v2 = 0.f, v3 = 0.f;
            if (n < NN) {
                float4 t = *(const float4*)&A[(size_t)n * K + k];
                if (PRE == 1) {
                    float ro = rs_of(g_deg_out[n]);
                    v0 = t.x * ro; v1 = t.y * ro; v2 = t.z * ro; v3 = t.w * ro;
                } else if (PRE == 2) {
                    float ri = rs_of(g_deg_in[n]), ro = rs_of(g_deg_out[n]);
                    float4 bb = *(const float4*)&bias[k];
                    v0 = fmaxf(fmaf(t.x, ri, bb.x), 0.f) * ro;
                    v1 = fmaxf(fmaf(t.y, ri, bb.y), 0.f) * ro;
                    v2 = fmaxf(fmaf(t.z, ri, bb.z), 0.f) * ro;
                    v3 = fmaxf(fmaf(t.w, ri, bb.w), 0.f) * ro;
                } else {
                    float ri = rs_of(g_deg_in[n]);
                    float4 bb = *(const float4*)&bias[k];
                    v0 = fmaf(t.x, ri, bb.x);
                    v1 = fmaf(t.y, ri, bb.y);
                    v2 = fmaf(t.z, ri, bb.z);
                    v3 = fmaf(t.w, ri, bb.w);
                }
            }
            int pr = nl >> 1, hh = nl & 1;
            int kb = kg * 4;
            xh[((kb + 0) * PSTRG + pr) * 2 + hh] = __float2half(v0);
            xh[((kb + 1) * PSTRG + pr) * 2 + hh] = __float2half(v1);
            xh[((kb + 2) * PSTRG + pr) * 2 + hh] = __float2half(v2);
            xh[((kb + 3) * PSTRG + pr) * 2 + hh] = __float2half(v3);
        }
        __syncthreads();
        // HFMA2 mainloop: two 16-k half chunks, promote to fp32 between
#pragma unroll
        for (int hc = 0; hc < 2; hc++) {
            __half2 acch[4][NPT];
#pragma unroll
            for (int q = 0; q < 4; q++)
#pragma unroll
                for (int c = 0; c < NPT; c++) acch[q][c] = hz;
#pragma unroll
            for (int kk = hc * 16; kk < hc * 16 + 16; kk++) {
                uint4 uw = *(const uint4*)&Ws2[kk * NOUT + tx * NPT];
                uint4 uz = *(const uint4*)&Xs2[kk * PSTRG + ty * 4];
                __half2 wv[4] = { *(__half2*)&uw.x, *(__half2*)&uw.y,
                                  *(__half2*)&uw.z, *(__half2*)&uw.w };
                __half2 zp[4] = { *(__half2*)&uz.x, *(__half2*)&uz.y,
                                  *(__half2*)&uz.z, *(__half2*)&uz.w };
#pragma unroll
                for (int q = 0; q < 4; q++)
#pragma unroll
                    for (int c = 0; c < NPT; c++)
                        acch[q][c] = __hfma2(zp[q], wv[c], acch[q][c]);
            }
#pragma unroll
            for (int q = 0; q < 4; q++)
#pragma unroll
                for (int c = 0; c < NPT; c++) {
                    float2 f = __half22float2(acch[q][c]);
                    accf[2 * q][c]     += f.x;
                    accf[2 * q + 1][c] += f.y;
                }
        }
        __syncthreads();
    }
    float4 eb = make_float4(0.f, 0.f, 0.f, 0.f);
    if (WMAP == 1 && tx >= 16) eb = *(const float4*)&ebias[tx * 4 - 64];
#pragma unroll
    for (int r = 0; r < RPT; r++) {
        int n = nb + ty * RPT + r;
        if (n < NN) {
            float o0 = accf[r][0] + eb.x, o1 = accf[r][1] + eb.y;
            float o2 = accf[r][2] + eb.z, o3 = accf[r][3] + eb.w;
            if (sizeof(OT) == 2) {
                __half2 p0 = __floats2half2_rn(o0, o1);
                __half2 p1 = __floats2half2_rn(o2, o3);
                unsigned u0 = *reinterpret_cast<unsigned*>(&p0);
                unsigned u1 = *reinterpret_cast<unsigned*>(&p1);
                *(uint2*)&C[(size_t)n * NOUT + tx * NPT] = make_uint2(u0, u1);
            } else {
                *(float4*)&C[(size_t)n * NOUT + tx * NPT] = make_float4(o0, o1, o2, o3);
            }
        }
    }
}

// ---------------- per-edge MLP, CSR(dst) order, HFMA2 phase B (R14) ----------------
#define PSTR 132   // pair stride (128 pairs + pad); multiple of 4 -> aligned uint4
__global__ __launch_bounds__(256) void edge_mlp_k(
    const float* __restrict__ Wp2, const float* __restrict__ bp2,
    const float* __restrict__ Wp3, const float* __restrict__ bp3,
    float* __restrict__ out)
{
    __shared__ __align__(16) __half2 z1s[64 * PSTR];   // [k][pair]
    __shared__ __align__(16) __half2 w2s[64 * 32];     // [k][n] broadcast (w,w)
    __shared__ float b2s[32];
    __shared__ float w3s[32];
    __shared__ float b3s;
    __shared__ int   eids[256];
    int tid = threadIdx.x;

    for (int i = tid; i < 64 * 32; i += 256) w2s[i] = __float2half2_rn(Wp2[i]);
    if (tid < 32)       b2s[tid]      = bp2[tid];
    else if (tid < 64)  w3s[tid - 32] = Wp3[tid - 32];
    if (tid == 64) b3s = bp3[0];

    int slot = blockIdx.x * 256 + tid;   // NE % 256 == 0
    int s = g_csr_src[slot], d = g_csr_dst[slot];
    eids[tid] = g_csr_eid[slot];
    const uint4* ps = (const uint4*)&g_pre[(size_t)s * 128];
    const uint4* pd = (const uint4*)&g_pre[(size_t)d * 128 + 64];
    int pr = tid >> 1, hh = tid & 1;
    __half* z1h = (__half*)z1s;
    const __half2 hz = __float2half2_rn(0.f);
#pragma unroll
    for (int g = 0; g < 8; g++) {
        uint4 ua = ps[g];
        uint4 uc = pd[g];
        __half2 zz[4];
        zz[0] = __hmax2(__hadd2(*(__half2*)&ua.x, *(__half2*)&uc.x), hz);
        zz[1] = __hmax2(__hadd2(*(__half2*)&ua.y, *(__half2*)&uc.y), hz);
        zz[2] = __hmax2(__hadd2(*(__half2*)&ua.z, *(__half2*)&uc.z), hz);
        zz[3] = __hmax2(__hadd2(*(__half2*)&ua.w, *(__half2*)&uc.w), hz);
#pragma unroll
        for (int q = 0; q < 4; q++) {
            int k0 = g * 8 + q * 2;
            z1h[(k0 * PSTR + pr) * 2 + hh]       = __low2half(zz[q]);
            z1h[((k0 + 1) * PSTR + pr) * 2 + hh] = __high2half(zz[q]);
        }
    }
    __syncthreads();

    int tx = tid & 7;
    int ey = tid >> 3;
    float accf[8][4];
#pragma unroll
    for (int r = 0; r < 8; r++)
#pragma unroll
        for (int c = 0; c < 4; c++) accf[r][c] = 0.f;

#pragma unroll
    for (int kc = 0; kc < 4; kc++) {
        __half2 acch[4][4];
#pragma unroll
        for (int p = 0; p < 4; p++)
#pragma unroll
            for (int c = 0; c < 4; c++) acch[p][c] = hz;
#pragma unroll
        for (int kk = 0; kk < 16; kk++) {
            int k = kc * 16 + kk;
            uint4 uw = *(const uint4*)&w2s[k * 32 + tx * 4];
            uint4 uz = *(const uint4*)&z1s[k * PSTR + ey * 4];
            __half2 wv[4] = { *(__half2*)&uw.x, *(__half2*)&uw.y,
                              *(__half2*)&uw.z, *(__half2*)&uw.w };
            __half2 zp[4] = { *(__half2*)&uz.x, *(__half2*)&uz.y,
                              *(__half2*)&uz.z, *(__half2*)&uz.w };
#pragma unroll
            for (int p = 0; p < 4; p++)
#pragma unroll
                for (int c = 0; c < 4; c++)
                    acch[p][c] = __hfma2(zp[p], wv[c], acch[p][c]);
        }
#pragma unroll
        for (int p = 0; p < 4; p++)
#pragma unroll
            for (int c = 0; c < 4; c++) {
                float2 f = __half22float2(acch[p][c]);
                accf[2 * p][c]     += f.x;
                accf[2 * p + 1][c] += f.y;
            }
    }

    float4 w3  = *(const float4*)&w3s[tx * 4];
    float4 bb2 = *(const float4*)&b2s[tx * 4];
    float pscore[8];
#pragma unroll
    for (int r = 0; r < 8; r++) {
        float q0 = fmaxf(accf[r][0] + bb2.x, 0.f);
        float q1 = fmaxf(accf[r][1] + bb2.y, 0.f);
        float q2 = fmaxf(accf[r][2] + bb2.z, 0.f);
        float q3 = fmaxf(accf[r][3] + bb2.w, 0.f);
        pscore[r] = q0 * w3.x + q1 * w3.y + q2 * w3.z + q3 * w3.w;
    }
#pragma unroll
    for (int off = 4; off >= 1; off >>= 1)
#pragma unroll
        for (int r = 0; r < 8; r++)
            pscore[r] += __shfl_down_sync(0xffffffffu, pscore[r], off, 8);

    if (tx == 0) {
#pragma unroll
        for (int r = 0; r < 8; r++) {
            float sc = pscore[r] + b3s;
            out[eids[ey * 8 + r]] = 1.f / (1.f + expf(-sc));
        }
    }
}

// ---------------- launch ----------------
extern "C" void kernel_launch(void* const* d_in, const int* in_sizes, int n_in,
                              void* d_out, int out_size) {
    const float* x   = (const float*)d_in[0];
    const void*  src = d_in[1];
    const void*  dst = d_in[2];
    const float* W1  = (const float*)d_in[3];
    const float* b1  = (const float*)d_in[4];
    const float* W2  = (const float*)d_in[5];
    const float* b2  = (const float*)d_in[6];
    const float* Wp1 = (const float*)d_in[7];
    const float* bp1 = (const float*)d_in[8];
    const float* Wp2 = (const float*)d_in[9];
    const float* bp2 = (const float*)d_in[10];
    const float* Wp3 = (const float*)d_in[11];
    const float* bp3 = (const float*)d_in[12];
    float* out = (float*)d_out;

    __half *h1tmp, *h2tmp, *pre;
    float *agg1, *agg2;
    cudaGetSymbolAddress((void**)&h1tmp, g_h1tmp);
    cudaGetSymbolAddress((void**)&agg1,  g_agg1);
    cudaGetSymbolAddress((void**)&h2tmp, g_h2tmp);
    cudaGetSymbolAddress((void**)&agg2,  g_agg2);
    cudaGetSymbolAddress((void**)&pre,   g_pre);

    // side stream + events, created on the first (non-captured) call
    static cudaStream_t s1 = nullptr;
    static cudaEvent_t evA = nullptr, evB = nullptr;
    if (s1 == nullptr) {
        cudaStreamCreateWithFlags(&s1, cudaStreamNonBlocking);
        cudaEventCreateWithFlags(&evA, cudaEventDisableTiming);
        cudaEventCreateWithFlags(&evB, cudaEventDisableTiming);
    }

    zero_k<<<512, 256>>>(src);
    convert_deg_k<<<NE / 256, 256>>>(src, dst);

    // fork: CSR build (scan + bin) on s1, overlapped with gemm1
    cudaEventRecord(evA, 0);
    cudaStreamWaitEvent(s1, evA, 0);
    scanA_k<<<NBLK_SCAN, 1024, 0, s1>>>();
    scanB_k<<<1, 128, 0, s1>>>();
    scanC_k<<<(NN + 255) / 256, 256, 0, s1>>>();
    bin_k<<<NE / 256, 256, 0, s1>>>();
    cudaEventRecord(evB, s1);

    gemm_k<128, 128, 64, 32, 1, 0><<<(NN + 63) / 64, 256>>>(x, W1, b1, nullptr, h1tmp);

    // join before aggregation needs the CSR
    cudaStreamWaitEvent(0, evB, 0);
    agg_k<128><<<(NN * 32 + 255) / 256, 256>>>(h1tmp, agg1);

    gemm_k<128, 64, 128, 16, 2, 0><<<(NN + 127) / 128, 256>>>(agg1, W2, b1, nullptr, h2tmp);
    agg_k<64><<<(NN * 32 + 255) / 256, 256>>>(h2tmp, agg2);

    // pre = (agg2*rs_in + b2) @ [Wp1_top | Wp1_bot]; +bp1 folded into cols 64..127
    gemm_k<64, 128, 64, 32, 3, 1><<<(NN + 63) / 64, 256>>>(agg2, Wp1, b2, bp1, pre);

    // per-edge MLP + sigmoid, CSR(dst) order, HFMA2 phase B
    edge_mlp_k<<<NE / 256, 256>>>(Wp2, bp2, Wp3, bp3, out);
}